// round 10
// baseline (speedup 1.0000x reference)
#include <cuda_runtime.h>
#include <math.h>

// Problem dims
#define Bb   64
#define Ss   512
#define Tt   64
#define Hh   512
#define Dd   512
#define G3   1536          // 3*H
#define HB   (Hh*Bb)       // 32768, one hidden state in [j][b] layout

// ---------------------------------------------------------------------------
// Scratch (device globals; no allocations allowed)
// ---------------------------------------------------------------------------
__device__ __align__(16) float g_gi[2][(size_t)Bb*Ss*G3];   // pre/post gate inputs [b][s][g]
__device__ __align__(16) float g_gid[(size_t)Bb*Tt*G3];     // decoder gate inputs  [b][t][g]
__device__ __align__(16) float g_hist[2][(size_t)(Ss+1)*HB];// encoder h history [t][j][b]
__device__ __align__(16) float g_dhist[(size_t)(Tt+1)*HB];  // decoder h history [t][j][b]
__device__ __align__(16) float g_score[Bb*2*Ss];            // score_enc [b][s2]
__device__ __align__(16) float g_hsc[Tt*Bb];                // decoder hidden scores [t][b]
__device__ int   g_dtok[Bb*Tt];                              // decoder input tokens

// ---------------------------------------------------------------------------
// init: zero h0 for both encoder GRUs
// ---------------------------------------------------------------------------
__global__ void init_kernel() {
    int i = blockIdx.x * blockDim.x + threadIdx.x;   // grid covers HB
    if (i < HB) { g_hist[0][i] = 0.f; g_hist[1][i] = 0.f; }
}

// ---------------------------------------------------------------------------
// decoder tokens: [pre_seq[:, -1:], trg[:, :-1]]
// ---------------------------------------------------------------------------
__global__ void dectok_kernel(const int* __restrict__ pre_seq,
                              const int* __restrict__ trg) {
    int idx = blockIdx.x * blockDim.x + threadIdx.x;   // 0..4095
    if (idx >= Bb * Tt) return;
    int b = idx >> 6, t = idx & 63;
    g_dtok[idx] = (t == 0) ? pre_seq[b * Ss + (Ss - 1)] : trg[b * Tt + t - 1];
}

// ---------------------------------------------------------------------------
// tf32 helpers
// ---------------------------------------------------------------------------
__device__ __forceinline__ unsigned f2tf(float x) {
    unsigned r; asm("cvt.rna.tf32.f32 %0, %1;" : "=r"(r) : "f"(x)); return r;
}
__device__ __forceinline__ void mma_tf32(float* d, const unsigned* a, const unsigned* b) {
    asm volatile(
        "mma.sync.aligned.m16n8k8.row.col.f32.tf32.tf32.f32 "
        "{%0,%1,%2,%3}, {%4,%5,%6,%7}, {%8,%9}, {%0,%1,%2,%3};"
        : "+f"(d[0]), "+f"(d[1]), "+f"(d[2]), "+f"(d[3])
        : "r"(a[0]), "r"(a[1]), "r"(a[2]), "r"(a[3]), "r"(b[0]), "r"(b[1]));
}

// ---------------------------------------------------------------------------
// Tensor-core fused gather-GEMM (tf32):
//   C[m][n] = sum_k emb[token[m]][k] * W[n][k] + bias[n]
// CTA tile 64(M)x64(N), K staged 32 at a time. 128 threads = 2x2 warps,
// each warp computes 32x32 via mma.m16n8k8 (2 m-frags x 4 n-frags).
// Inputs converted fp32->tf32 (cvt.rna, unbiased) once during staging.
// smem [row][k] padded to 36 words: fragment reads hit banks (grp*4+q)%32
// -> conflict-free. Register prefetch overlaps next-stage global loads.
// dst: 0=gi_pre 1=gi_post 2=gi_dec
// ---------------------------------------------------------------------------
__global__ __launch_bounds__(128, 4) void gemm_gather_tc(
    const int* __restrict__ tokens_arg, int dst,
    const float* __restrict__ emb,
    const float* __restrict__ W,
    const float* __restrict__ bias)
{
    const int* tokens = (dst == 2) ? g_dtok : tokens_arg;
    float* C = (dst == 0) ? g_gi[0] : (dst == 1) ? g_gi[1] : g_gid;

    __shared__ __align__(16) unsigned As[64][36];   // [m][k] tf32 bits
    __shared__ __align__(16) unsigned Bs[64][36];   // [n][k] tf32 bits

    int tid = threadIdx.x;
    int m0 = blockIdx.x * 64;
    int n0 = blockIdx.y * 64;

    // staging assignment: row = tid>>1 (0..63), half = tid&1 -> k words [half*16, half*16+16)
    int srow = tid >> 1;
    int sk0  = (tid & 1) << 4;          // 0 or 16

    int tokm = tokens[m0 + srow];
    const float* arow = emb + (size_t)tokm * Dd + sk0;
    const float* brow = W + (size_t)(n0 + srow) * Dd + sk0;

    // warp/lane decomposition
    int w = tid >> 5;
    int wm = (w >> 1) << 5;             // 0 or 32 (warp m-offset)
    int wn = (w & 1) << 5;              // 0 or 32 (warp n-offset)
    int lane = tid & 31;
    int grp = lane >> 2;                // 0..7
    int q   = lane & 3;                 // 0..3

    float acc[2][4][4];
    #pragma unroll
    for (int mi = 0; mi < 2; mi++)
        #pragma unroll
        for (int ni = 0; ni < 4; ni++)
            #pragma unroll
            for (int r = 0; r < 4; r++) acc[mi][ni][r] = 0.f;

    // prefetch first K-stage (4 float4 per operand per thread)
    float4 pa0 = *(const float4*)(arow + 0);
    float4 pa1 = *(const float4*)(arow + 4);
    float4 pa2 = *(const float4*)(arow + 8);
    float4 pa3 = *(const float4*)(arow + 12);
    float4 pb0 = *(const float4*)(brow + 0);
    float4 pb1 = *(const float4*)(brow + 4);
    float4 pb2 = *(const float4*)(brow + 8);
    float4 pb3 = *(const float4*)(brow + 12);

    for (int k0 = 0; k0 < Dd; k0 += 32) {
        __syncthreads();
        // store stage with fp32->tf32 conversion (packed uint4 stores)
        uint4* adst = (uint4*)&As[srow][sk0];
        uint4* bdst = (uint4*)&Bs[srow][sk0];
        adst[0] = make_uint4(f2tf(pa0.x), f2tf(pa0.y), f2tf(pa0.z), f2tf(pa0.w));
        adst[1] = make_uint4(f2tf(pa1.x), f2tf(pa1.y), f2tf(pa1.z), f2tf(pa1.w));
        adst[2] = make_uint4(f2tf(pa2.x), f2tf(pa2.y), f2tf(pa2.z), f2tf(pa2.w));
        adst[3] = make_uint4(f2tf(pa3.x), f2tf(pa3.y), f2tf(pa3.z), f2tf(pa3.w));
        bdst[0] = make_uint4(f2tf(pb0.x), f2tf(pb0.y), f2tf(pb0.z), f2tf(pb0.w));
        bdst[1] = make_uint4(f2tf(pb1.x), f2tf(pb1.y), f2tf(pb1.z), f2tf(pb1.w));
        bdst[2] = make_uint4(f2tf(pb2.x), f2tf(pb2.y), f2tf(pb2.z), f2tf(pb2.w));
        bdst[3] = make_uint4(f2tf(pb3.x), f2tf(pb3.y), f2tf(pb3.z), f2tf(pb3.w));
        __syncthreads();

        if (k0 + 32 < Dd) {             // prefetch next stage (overlaps mma)
            pa0 = *(const float4*)(arow + k0 + 32);
            pa1 = *(const float4*)(arow + k0 + 36);
            pa2 = *(const float4*)(arow + k0 + 40);
            pa3 = *(const float4*)(arow + k0 + 44);
            pb0 = *(const float4*)(brow + k0 + 32);
            pb1 = *(const float4*)(brow + k0 + 36);
            pb2 = *(const float4*)(brow + k0 + 40);
            pb3 = *(const float4*)(brow + k0 + 44);
        }

        #pragma unroll
        for (int ks = 0; ks < 4; ks++) {
            int kb = ks * 8;
            unsigned a[2][4], b[4][2];
            #pragma unroll
            for (int mi = 0; mi < 2; mi++) {
                int m = wm + mi * 16;
                a[mi][0] = As[m + grp][kb + q];
                a[mi][1] = As[m + grp + 8][kb + q];
                a[mi][2] = As[m + grp][kb + q + 4];
                a[mi][3] = As[m + grp + 8][kb + q + 4];
            }
            #pragma unroll
            for (int ni = 0; ni < 4; ni++) {
                int n = wn + ni * 8;
                b[ni][0] = Bs[n + grp][kb + q];
                b[ni][1] = Bs[n + grp][kb + q + 4];
            }
            #pragma unroll
            for (int mi = 0; mi < 2; mi++)
                #pragma unroll
                for (int ni = 0; ni < 4; ni++)
                    mma_tf32(acc[mi][ni], a[mi], b[ni]);
        }
    }

    // epilogue: D-fragment rows (grp, grp+8), cols (2q, 2q+1) per n-frag
    #pragma unroll
    for (int mi = 0; mi < 2; mi++) {
        int mrow = m0 + wm + mi * 16 + grp;
        #pragma unroll
        for (int ni = 0; ni < 4; ni++) {
            int ncol = n0 + wn + ni * 8 + q * 2;
            float b0 = bias[ncol], b1 = bias[ncol + 1];
            *(float2*)&C[(size_t)mrow * G3 + ncol] =
                make_float2(acc[mi][ni][0] + b0, acc[mi][ni][1] + b1);
            *(float2*)&C[(size_t)(mrow + 8) * G3 + ncol] =
                make_float2(acc[mi][ni][2] + b0, acc[mi][ni][3] + b1);
        }
    }
}

// ---------------------------------------------------------------------------
// GRU step (R4-exact, the measured-best recurrence).
// CTA owns 8 h-columns; Whh slice (24 rows x 512) staged in smem (48KB).
// 256 threads: jj = tid>>5 (0..7), bg = tid&31 -> 2 batches (bg*2, bg*2+1).
// h layout [j][b] (j-major), so h reads are coalesced.
// ---------------------------------------------------------------------------
#define FMA2(hv, wrv, wzv, wnv)                                               \
    accr[0] += hv.x * wrv; accr[1] += hv.y * wrv;                             \
    accz[0] += hv.x * wzv; accz[1] += hv.y * wzv;                             \
    accn[0] += hv.x * wnv; accn[1] += hv.y * wnv;

__device__ __forceinline__ float fsigmoid(float x) {
    return 1.f / (1.f + __expf(-x));
}

__global__ __launch_bounds__(256) void gru_step(
    int isDec, int t,
    const float* __restrict__ Whh0, const float* __restrict__ Whh1,
    const float* __restrict__ bhh0, const float* __restrict__ bhh1)
{
    int gru = blockIdx.y;
    const float* gi  = isDec ? g_gid : g_gi[gru];
    float* hist      = isDec ? g_dhist : g_hist[gru];
    const float* Whh = gru ? Whh1 : Whh0;
    const float* bhh = gru ? bhh1 : bhh0;
    int seq = isDec ? Tt : Ss;

    const float* h_in = hist + (size_t)t * HB;
    float* h_out      = hist + (size_t)(t + 1) * HB;

    __shared__ __align__(16) float sw[24 * 512];   // exactly 48KB
    int tid = threadIdx.x;
    int j0 = blockIdx.x * 8;
    {
        const float4* W4 = (const float4*)Whh;
        float4* sw4 = (float4*)sw;
        #pragma unroll
        for (int i = 0; i < 12; i++) {
            int idx = i * 256 + tid;          // 0..3071 float4s
            int r = idx >> 7, c = idx & 127;
            int gate = r >> 3, jj = r & 7;
            int row = gate * Hh + j0 + jj;
            sw4[idx] = W4[(size_t)row * 128 + c];
        }
    }
    __syncthreads();

    int jj = tid >> 5;    // 0..7
    int bg = tid & 31;    // 0..31 -> batch pair (2*bg, 2*bg+1)
    const float2* h2  = (const float2*)h_in;
    const float4* swr = (const float4*)(sw + jj * 512);
    const float4* swz = (const float4*)(sw + (8 + jj) * 512);
    const float4* swn = (const float4*)(sw + (16 + jj) * 512);

    float accr[2] = {0.f, 0.f};
    float accz[2] = {0.f, 0.f};
    float accn[2] = {0.f, 0.f};

    #pragma unroll 4
    for (int k4 = 0; k4 < 128; k4++) {
        float4 wr = swr[k4], wz = swz[k4], wn = swn[k4];
        float2 hA = h2[(k4 * 4 + 0) * 32 + bg];
        float2 hB = h2[(k4 * 4 + 1) * 32 + bg];
        float2 hC = h2[(k4 * 4 + 2) * 32 + bg];
        float2 hD = h2[(k4 * 4 + 3) * 32 + bg];
        FMA2(hA, wr.x, wz.x, wn.x)
        FMA2(hB, wr.y, wz.y, wn.y)
        FMA2(hC, wr.z, wz.z, wn.z)
        FMA2(hD, wr.w, wz.w, wn.w)
    }

    int j = j0 + jj;
    float br = bhh[j], bz = bhh[Hh + j], bn = bhh[2 * Hh + j];
    float2 hold = h2[j * 32 + bg];
    float holdv[2] = {hold.x, hold.y};
    float ho[2];
    #pragma unroll
    for (int i = 0; i < 2; i++) {
        int b = bg * 2 + i;
        const float* g = gi + ((size_t)b * seq + t) * G3;
        float r = fsigmoid(g[j]          + accr[i] + br);
        float z = fsigmoid(g[Hh + j]     + accz[i] + bz);
        float n = tanhf(g[2 * Hh + j] + r * (accn[i] + bn));
        ho[i] = (1.f - z) * n + z * holdv[i];
    }
    *(float2*)&h_out[j * Bb + bg * 2] = make_float2(ho[0], ho[1]);
}

// ---------------------------------------------------------------------------
// score_enc[b][gru*S + t] = sum_j relu(h_{t+1}[j][b]) * w_enc[j]
// ---------------------------------------------------------------------------
__global__ __launch_bounds__(64) void score_kernel(const float* __restrict__ out_w) {
    int t = blockIdx.x, gru = blockIdx.y, b = threadIdx.x;
    const float* hrow = g_hist[gru] + (size_t)(t + 1) * HB;
    float acc = 0.f;
    for (int j = 0; j < Hh; j++)
        acc += fmaxf(hrow[j * Bb + b], 0.f) * out_w[j];
    g_score[b * (2 * Ss) + gru * Ss + t] = acc;
}

// ---------------------------------------------------------------------------
// enc_hidden (decoder h0) = tanh(cat(pre_h, post_h) @ enc_fc_w^T + enc_fc_b)
// ---------------------------------------------------------------------------
__global__ __launch_bounds__(64) void ench_kernel(const float* __restrict__ enc_fc_w,
                                                  const float* __restrict__ enc_fc_b) {
    int i = blockIdx.x, b = threadIdx.x;
    const float* w = enc_fc_w + (size_t)i * (2 * Hh);
    const float* hp0 = g_hist[0] + (size_t)Ss * HB;
    const float* hp1 = g_hist[1] + (size_t)Ss * HB;
    float acc = enc_fc_b[i];
    for (int q = 0; q < Hh; q++) acc += hp0[q * Bb + b] * w[q];
    for (int q = 0; q < Hh; q++) acc += hp1[q * Bb + b] * w[Hh + q];
    g_dhist[i * Bb + b] = tanhf(acc);
}

// ---------------------------------------------------------------------------
// decoder hidden score: hsc[t][b] = relu(hdec_{t+1}[:,b]) . w_hid + out_b
// ---------------------------------------------------------------------------
__global__ __launch_bounds__(64) void hsc_kernel(const float* __restrict__ out_w,
                                                 const float* __restrict__ out_b) {
    int t = blockIdx.x, b = threadIdx.x;
    const float* hrow = g_dhist + (size_t)(t + 1) * HB;
    float acc = 0.f;
    for (int j = 0; j < Hh; j++)
        acc += fmaxf(hrow[j * Bb + b], 0.f) * out_w[Hh + j];
    g_hsc[t * Bb + b] = acc + out_b[0];
}

// ---------------------------------------------------------------------------
// probs: out_pre[b][t][s] = sigmoid(score[b][s] + hsc[t][b]); post analogous
// ---------------------------------------------------------------------------
__global__ __launch_bounds__(256) void probs_kernel(float* __restrict__ out) {
    int bt = blockIdx.x;             // 0..4095
    int b = bt >> 6, t = bt & 63;
    float hs = g_hsc[t * Bb + b];
    const float* sc = g_score + b * (2 * Ss);
    float* out_pre  = out + (size_t)bt * Ss;
    float* out_post = out + (size_t)Bb * Tt * Ss + (size_t)bt * Ss;
    #pragma unroll
    for (int it = 0; it < 4; it++) {
        int s2 = it * 256 + threadIdx.x;
        float l = sc[s2] + hs;
        float p = 1.f / (1.f + expf(-l));
        if (s2 < Ss) out_pre[s2] = p;
        else         out_post[s2 - Ss] = p;
    }
}

// ---------------------------------------------------------------------------
// launch
// ---------------------------------------------------------------------------
extern "C" void kernel_launch(void* const* d_in, const int* in_sizes, int n_in,
                              void* d_out, int out_size) {
    const int*   pre_seq   = (const int*)  d_in[0];
    const int*   post_seq  = (const int*)  d_in[1];
    const int*   trg       = (const int*)  d_in[2];
    const float* emb       = (const float*)d_in[3];
    const float* pre_Wih   = (const float*)d_in[4];
    const float* pre_Whh   = (const float*)d_in[5];
    const float* pre_bih   = (const float*)d_in[6];
    const float* pre_bhh   = (const float*)d_in[7];
    const float* post_Wih  = (const float*)d_in[8];
    const float* post_Whh  = (const float*)d_in[9];
    const float* post_bih  = (const float*)d_in[10];
    const float* post_bhh  = (const float*)d_in[11];
    const float* enc_fc_w  = (const float*)d_in[12];
    const float* enc_fc_b  = (const float*)d_in[13];
    const float* dec_Wih   = (const float*)d_in[14];
    const float* dec_Whh   = (const float*)d_in[15];
    const float* dec_bih   = (const float*)d_in[16];
    const float* dec_bhh   = (const float*)d_in[17];
    const float* out_w     = (const float*)d_in[18];
    const float* out_b     = (const float*)d_in[19];
    float* out = (float*)d_out;

    // h0 = 0 and decoder token assembly
    init_kernel<<<128, 256>>>();
    dectok_kernel<<<16, 256>>>(pre_seq, trg);

    // Gate-input GEMMs (tensor-core tf32, fused embedding gather)
    gemm_gather_tc<<<dim3(Bb * Ss / 64, G3 / 64), 128>>>(pre_seq,  0, emb, pre_Wih,  pre_bih);
    gemm_gather_tc<<<dim3(Bb * Ss / 64, G3 / 64), 128>>>(post_seq, 1, emb, post_Wih, post_bih);
    gemm_gather_tc<<<dim3(Bb * Tt / 64, G3 / 64), 128>>>(nullptr,  2, emb, dec_Wih,  dec_bih);

    // Encoder recurrences (pre + post in one grid per step)
    for (int t = 0; t < Ss; t++)
        gru_step<<<dim3(Hh / 8, 2), 256>>>(0, t, pre_Whh, post_Whh, pre_bhh, post_bhh);

    // score_enc over all encoder outputs; decoder initial hidden
    score_kernel<<<dim3(Ss, 2), 64>>>(out_w);
    ench_kernel<<<Hh, 64>>>(enc_fc_w, enc_fc_b);

    // Decoder recurrence
    for (int t = 0; t < Tt; t++)
        gru_step<<<dim3(Hh / 8, 1), 256>>>(1, t, dec_Whh, dec_Whh, dec_bhh, dec_bhh);

    // Logits -> probabilities -> output
    hsc_kernel<<<Tt, 64>>>(out_w, out_b);
    probs_kernel<<<Bb * Tt, 256>>>(out);
}

// round 12
// speedup vs baseline: 1.2564x; 1.2564x over previous
#include <cuda_runtime.h>
#include <cuda_bf16.h>
#include <math.h>
#include <stdint.h>

// Problem dims
#define Bb   64
#define Ss   512
#define Tt   64
#define Hh   512
#define Dd   512
#define G3   1536          // 3*H
#define HB   (Hh*Bb)       // 32768, one hidden state in [j][b] layout
#define Vv   32000

// ---------------------------------------------------------------------------
// Scratch (device globals; no allocations allowed)
// ---------------------------------------------------------------------------
__device__ __align__(16) float g_gi[2][(size_t)Bb*Ss*G3];   // pre/post gate inputs [b][s][g]
__device__ __align__(16) float g_gid[(size_t)Bb*Tt*G3];     // decoder gate inputs  [b][t][g]
__device__ __align__(16) float g_hist[2][(size_t)(Ss+1)*HB];// encoder h history [t][j][b]
__device__ __align__(16) float g_dhist[(size_t)(Tt+1)*HB];  // decoder h history [t][j][b]
__device__ __align__(16) float g_score[Bb*2*Ss];            // score_enc [b][s2]
__device__ __align__(16) float g_hsc[Tt*Bb];                // decoder hidden scores [t][b]
__device__ int   g_dtok[Bb*Tt];                             // decoder input tokens

// bf16 operands for the tensor-core gate GEMMs
__device__ __align__(16) __nv_bfloat16 g_emb_bf[(size_t)Vv*Dd];
__device__ __align__(16) __nv_bfloat16 g_w_bf[3][(size_t)G3*Dd];

// ---------------------------------------------------------------------------
// init: zero h0 for both encoder GRUs
// ---------------------------------------------------------------------------
__global__ void init_kernel() {
    int i = blockIdx.x * blockDim.x + threadIdx.x;
    if (i < HB) { g_hist[0][i] = 0.f; g_hist[1][i] = 0.f; }
}

// decoder tokens: [pre_seq[:, -1:], trg[:, :-1]]
__global__ void dectok_kernel(const int* __restrict__ pre_seq,
                              const int* __restrict__ trg) {
    int idx = blockIdx.x * blockDim.x + threadIdx.x;
    if (idx >= Bb * Tt) return;
    int b = idx >> 6, t = idx & 63;
    g_dtok[idx] = (t == 0) ? pre_seq[b * Ss + (Ss - 1)] : trg[b * Tt + t - 1];
}

// fp32 -> bf16 conversion. which: 0=emb, 1..3 = W[0..2]
__global__ void prep_kernel(const float* __restrict__ src, int which, int n) {
    int i = blockIdx.x * blockDim.x + threadIdx.x;
    if (i >= n) return;
    __nv_bfloat16* d = (which == 0) ? g_emb_bf : g_w_bf[which - 1];
    d[i] = __float2bfloat16(src[i]);
}

// ---------------------------------------------------------------------------
// bf16 mma.sync m16n8k16 (HMMA path; compiles at the harness's compute_103
// family target, unlike arch-specific tcgen05)
// ---------------------------------------------------------------------------
__device__ __forceinline__ void mma_bf16(float* d, const unsigned* a, const unsigned* b) {
    asm volatile(
        "mma.sync.aligned.m16n8k16.row.col.f32.bf16.bf16.f32 "
        "{%0,%1,%2,%3}, {%4,%5,%6,%7}, {%8,%9}, {%0,%1,%2,%3};"
        : "+f"(d[0]), "+f"(d[1]), "+f"(d[2]), "+f"(d[3])
        : "r"(a[0]), "r"(a[1]), "r"(a[2]), "r"(a[3]), "r"(b[0]), "r"(b[1]));
}

// ---------------------------------------------------------------------------
// Tensor-core fused gather-GEMM (bf16, m16n8k16):
//   C[m][n] = sum_k emb[token[m]][k] * W[n][k] + bias[n]
// CTA tile 128(M)x128(N), K staged 32 at a time, double-buffered smem.
// 256 threads = 8 warps (4m x 2n), warp tile 32x64 = 2 m-frags x 8 n-frags.
// Smem [row][k] pitch 40 bf16 (20 words): all fragment-read bank patterns
// (grp*20+q, grp*20+q+4 mod 32) verified conflict-free. Each fragment reg is
// one aligned b32 LDS (2 consecutive-k bf16). Register prefetch of the next
// stage overlaps the global loads with mma. dst: 0=gi_pre 1=gi_post 2=gi_dec
// ---------------------------------------------------------------------------
#define KP 40                      // row pitch in bf16 (20 words)
__global__ __launch_bounds__(256, 2) void gemm_gather_bf(
    const int* __restrict__ tokens_arg, int dst,
    const float* __restrict__ bias)
{
    __shared__ __align__(16) __nv_bfloat16 As[2][128 * KP];
    __shared__ __align__(16) __nv_bfloat16 Bs[2][128 * KP];

    int tid = threadIdx.x;
    const int* tokens = (dst == 2) ? g_dtok : tokens_arg;
    float* C = (dst == 0) ? g_gi[0] : (dst == 1) ? g_gi[1] : g_gid;
    const __nv_bfloat16* W = g_w_bf[dst];

    int m0 = blockIdx.x * 128;
    int n0 = blockIdx.y * 128;

    // staging: thread -> row = tid>>1 (0..127), seg = tid&1 (16-bf16 half of 32)
    int row = tid >> 1;
    int seg = tid & 1;
    int tok = tokens[m0 + row];
    const __nv_bfloat16* arow = g_emb_bf + (size_t)tok * Dd + seg * 16;
    const __nv_bfloat16* brow = W + (size_t)(n0 + row) * Dd + seg * 16;
    int sdst = row * KP + seg * 16;     // bf16 index into As/Bs

    // warp/lane decomposition
    int w = tid >> 5;
    int wm = (w >> 1) << 5;             // 0,32,64,96
    int wn = (w & 1) << 6;              // 0 or 64
    int lane = tid & 31;
    int grp = lane >> 2;                // 0..7
    int q   = lane & 3;                 // 0..3

    float acc[2][8][4];
    #pragma unroll
    for (int mi = 0; mi < 2; mi++)
        #pragma unroll
        for (int ni = 0; ni < 8; ni++)
            #pragma unroll
            for (int r = 0; r < 4; r++) acc[mi][ni][r] = 0.f;

    // prefetch first stage (2 uint4 = 16 bf16 per operand per thread)
    uint4 pa0 = *(const uint4*)(arow);
    uint4 pa1 = *(const uint4*)(arow + 8);
    uint4 pb0 = *(const uint4*)(brow);
    uint4 pb1 = *(const uint4*)(brow + 8);

    for (int k0 = 0; k0 < Dd; k0 += 32) {
        int buf = (k0 >> 5) & 1;
        *(uint4*)&As[buf][sdst]     = pa0;
        *(uint4*)&As[buf][sdst + 8] = pa1;
        *(uint4*)&Bs[buf][sdst]     = pb0;
        *(uint4*)&Bs[buf][sdst + 8] = pb1;
        __syncthreads();

        if (k0 + 32 < Dd) {             // prefetch next stage (overlaps mma)
            pa0 = *(const uint4*)(arow + k0 + 32);
            pa1 = *(const uint4*)(arow + k0 + 40);
            pb0 = *(const uint4*)(brow + k0 + 32);
            pb1 = *(const uint4*)(brow + k0 + 40);
        }

        const unsigned* Aw = (const unsigned*)As[buf];
        const unsigned* Bw = (const unsigned*)Bs[buf];
        #pragma unroll
        for (int ks = 0; ks < 2; ks++) {       // two k16 slices per stage
            int kb = ks * 8;                   // word offset of slice
            unsigned a[2][4], b[8][2];
            #pragma unroll
            for (int mi = 0; mi < 2; mi++) {
                int r0 = (wm + mi * 16 + grp) * 20;
                int r1 = (wm + mi * 16 + grp + 8) * 20;
                a[mi][0] = Aw[r0 + kb + q];
                a[mi][1] = Aw[r1 + kb + q];
                a[mi][2] = Aw[r0 + kb + q + 4];
                a[mi][3] = Aw[r1 + kb + q + 4];
            }
            #pragma unroll
            for (int ni = 0; ni < 8; ni++) {
                int rn = (wn + ni * 8 + grp) * 20;
                b[ni][0] = Bw[rn + kb + q];
                b[ni][1] = Bw[rn + kb + q + 4];
            }
            #pragma unroll
            for (int mi = 0; mi < 2; mi++)
                #pragma unroll
                for (int ni = 0; ni < 8; ni++)
                    mma_bf16(acc[mi][ni], a[mi], b[ni]);
        }
        __syncthreads();
    }

    // epilogue: D rows (grp, grp+8), cols (2q, 2q+1) per n-frag
    #pragma unroll
    for (int mi = 0; mi < 2; mi++) {
        int mrow = m0 + wm + mi * 16 + grp;
        #pragma unroll
        for (int ni = 0; ni < 8; ni++) {
            int ncol = n0 + wn + ni * 8 + q * 2;
            float b0 = bias[ncol], b1 = bias[ncol + 1];
            *(float2*)&C[(size_t)mrow * G3 + ncol] =
                make_float2(acc[mi][ni][0] + b0, acc[mi][ni][1] + b1);
            *(float2*)&C[(size_t)(mrow + 8) * G3 + ncol] =
                make_float2(acc[mi][ni][2] + b0, acc[mi][ni][3] + b1);
        }
    }
}

// ---------------------------------------------------------------------------
// GRU step (R4-exact, measured-best recurrence). 48KB static smem.
// ---------------------------------------------------------------------------
#define FMA2(hv, wrv, wzv, wnv)                                               \
    accr[0] += hv.x * wrv; accr[1] += hv.y * wrv;                             \
    accz[0] += hv.x * wzv; accz[1] += hv.y * wzv;                             \
    accn[0] += hv.x * wnv; accn[1] += hv.y * wnv;

__device__ __forceinline__ float fsigmoid(float x) {
    return 1.f / (1.f + __expf(-x));
}

__global__ __launch_bounds__(256) void gru_step(
    int isDec, int t,
    const float* __restrict__ Whh0, const float* __restrict__ Whh1,
    const float* __restrict__ bhh0, const float* __restrict__ bhh1)
{
    int gru = blockIdx.y;
    const float* gi  = isDec ? g_gid : g_gi[gru];
    float* hist      = isDec ? g_dhist : g_hist[gru];
    const float* Whh = gru ? Whh1 : Whh0;
    const float* bhh = gru ? bhh1 : bhh0;
    int seq = isDec ? Tt : Ss;

    const float* h_in = hist + (size_t)t * HB;
    float* h_out      = hist + (size_t)(t + 1) * HB;

    __shared__ __align__(16) float sw[24 * 512];
    int tid = threadIdx.x;
    int j0 = blockIdx.x * 8;
    {
        const float4* W4 = (const float4*)Whh;
        float4* sw4 = (float4*)sw;
        #pragma unroll
        for (int i = 0; i < 12; i++) {
            int idx = i * 256 + tid;
            int r = idx >> 7, c = idx & 127;
            int gate = r >> 3, jj = r & 7;
            int rowi = gate * Hh + j0 + jj;
            sw4[idx] = W4[(size_t)rowi * 128 + c];
        }
    }
    __syncthreads();

    int jj = tid >> 5;
    int bg = tid & 31;
    const float2* h2  = (const float2*)h_in;
    const float4* swr = (const float4*)(sw + jj * 512);
    const float4* swz = (const float4*)(sw + (8 + jj) * 512);
    const float4* swn = (const float4*)(sw + (16 + jj) * 512);

    float accr[2] = {0.f, 0.f};
    float accz[2] = {0.f, 0.f};
    float accn[2] = {0.f, 0.f};

    #pragma unroll 4
    for (int k4 = 0; k4 < 128; k4++) {
        float4 wr = swr[k4], wz = swz[k4], wn = swn[k4];
        float2 hA = h2[(k4 * 4 + 0) * 32 + bg];
        float2 hB = h2[(k4 * 4 + 1) * 32 + bg];
        float2 hC = h2[(k4 * 4 + 2) * 32 + bg];
        float2 hD = h2[(k4 * 4 + 3) * 32 + bg];
        FMA2(hA, wr.x, wz.x, wn.x)
        FMA2(hB, wr.y, wz.y, wn.y)
        FMA2(hC, wr.z, wz.z, wn.z)
        FMA2(hD, wr.w, wz.w, wn.w)
    }

    int j = j0 + jj;
    float br = bhh[j], bz = bhh[Hh + j], bn = bhh[2 * Hh + j];
    float2 hold = h2[j * 32 + bg];
    float holdv[2] = {hold.x, hold.y};
    float ho[2];
    #pragma unroll
    for (int i = 0; i < 2; i++) {
        int b = bg * 2 + i;
        const float* g = gi + ((size_t)b * seq + t) * G3;
        float r = fsigmoid(g[j]          + accr[i] + br);
        float z = fsigmoid(g[Hh + j]     + accz[i] + bz);
        float n = tanhf(g[2 * Hh + j] + r * (accn[i] + bn));
        ho[i] = (1.f - z) * n + z * holdv[i];
    }
    *(float2*)&h_out[j * Bb + bg * 2] = make_float2(ho[0], ho[1]);
}

// ---------------------------------------------------------------------------
// score_enc[b][gru*S + t] = sum_j relu(h_{t+1}[j][b]) * w_enc[j]
// ---------------------------------------------------------------------------
__global__ __launch_bounds__(64) void score_kernel(const float* __restrict__ out_w) {
    int t = blockIdx.x, gru = blockIdx.y, b = threadIdx.x;
    const float* hrow = g_hist[gru] + (size_t)(t + 1) * HB;
    float acc = 0.f;
    for (int j = 0; j < Hh; j++)
        acc += fmaxf(hrow[j * Bb + b], 0.f) * out_w[j];
    g_score[b * (2 * Ss) + gru * Ss + t] = acc;
}

// ---------------------------------------------------------------------------
// enc_hidden (decoder h0) = tanh(cat(pre_h, post_h) @ enc_fc_w^T + enc_fc_b)
// ---------------------------------------------------------------------------
__global__ __launch_bounds__(64) void ench_kernel(const float* __restrict__ enc_fc_w,
                                                  const float* __restrict__ enc_fc_b) {
    int i = blockIdx.x, b = threadIdx.x;
    const float* w = enc_fc_w + (size_t)i * (2 * Hh);
    const float* hp0 = g_hist[0] + (size_t)Ss * HB;
    const float* hp1 = g_hist[1] + (size_t)Ss * HB;
    float acc = enc_fc_b[i];
    for (int q = 0; q < Hh; q++) acc += hp0[q * Bb + b] * w[q];
    for (int q = 0; q < Hh; q++) acc += hp1[q * Bb + b] * w[Hh + q];
    g_dhist[i * Bb + b] = tanhf(acc);
}

// ---------------------------------------------------------------------------
// decoder hidden score: hsc[t][b] = relu(hdec_{t+1}[:,b]) . w_hid + out_b
// ---------------------------------------------------------------------------
__global__ __launch_bounds__(64) void hsc_kernel(const float* __restrict__ out_w,
                                                 const float* __restrict__ out_b) {
    int t = blockIdx.x, b = threadIdx.x;
    const float* hrow = g_dhist + (size_t)(t + 1) * HB;
    float acc = 0.f;
    for (int j = 0; j < Hh; j++)
        acc += fmaxf(hrow[j * Bb + b], 0.f) * out_w[Hh + j];
    g_hsc[t * Bb + b] = acc + out_b[0];
}

// ---------------------------------------------------------------------------
// probs: out_pre[b][t][s] = sigmoid(score[b][s] + hsc[t][b]); post analogous
// ---------------------------------------------------------------------------
__global__ __launch_bounds__(256) void probs_kernel(float* __restrict__ out) {
    int bt = blockIdx.x;
    int b = bt >> 6, t = bt & 63;
    float hs = g_hsc[t * Bb + b];
    const float* sc = g_score + b * (2 * Ss);
    float* out_pre  = out + (size_t)bt * Ss;
    float* out_post = out + (size_t)Bb * Tt * Ss + (size_t)bt * Ss;
    #pragma unroll
    for (int it = 0; it < 4; it++) {
        int s2 = it * 256 + threadIdx.x;
        float l = sc[s2] + hs;
        float p = 1.f / (1.f + expf(-l));
        if (s2 < Ss) out_pre[s2] = p;
        else         out_post[s2 - Ss] = p;
    }
}

// ---------------------------------------------------------------------------
// launch
// ---------------------------------------------------------------------------
extern "C" void kernel_launch(void* const* d_in, const int* in_sizes, int n_in,
                              void* d_out, int out_size) {
    const int*   pre_seq   = (const int*)  d_in[0];
    const int*   post_seq  = (const int*)  d_in[1];
    const int*   trg       = (const int*)  d_in[2];
    const float* emb       = (const float*)d_in[3];
    const float* pre_Wih   = (const float*)d_in[4];
    const float* pre_Whh   = (const float*)d_in[5];
    const float* pre_bih   = (const float*)d_in[6];
    const float* pre_bhh   = (const float*)d_in[7];
    const float* post_Wih  = (const float*)d_in[8];
    const float* post_Whh  = (const float*)d_in[9];
    const float* post_bih  = (const float*)d_in[10];
    const float* post_bhh  = (const float*)d_in[11];
    const float* enc_fc_w  = (const float*)d_in[12];
    const float* enc_fc_b  = (const float*)d_in[13];
    const float* dec_Wih   = (const float*)d_in[14];
    const float* dec_Whh   = (const float*)d_in[15];
    const float* dec_bih   = (const float*)d_in[16];
    const float* dec_bhh   = (const float*)d_in[17];
    const float* out_w     = (const float*)d_in[18];
    const float* out_b     = (const float*)d_in[19];
    float* out = (float*)d_out;

    // h0 = 0, decoder tokens, bf16 conversions
    init_kernel<<<128, 256>>>();
    dectok_kernel<<<16, 256>>>(pre_seq, trg);
    prep_kernel<<<(Vv * Dd + 255) / 256, 256>>>(emb, 0, Vv * Dd);
    prep_kernel<<<(G3 * Dd + 255) / 256, 256>>>(pre_Wih,  1, G3 * Dd);
    prep_kernel<<<(G3 * Dd + 255) / 256, 256>>>(post_Wih, 2, G3 * Dd);
    prep_kernel<<<(G3 * Dd + 255) / 256, 256>>>(dec_Wih,  3, G3 * Dd);

    // Gate-input GEMMs (bf16 tensor-core mma, fused embedding gather)
    gemm_gather_bf<<<dim3(Bb * Ss / 128, G3 / 128), 256>>>(pre_seq,  0, pre_bih);
    gemm_gather_bf<<<dim3(Bb * Ss / 128, G3 / 128), 256>>>(post_seq, 1, post_bih);
    gemm_gather_bf<<<dim3(Bb * Tt / 128, G3 / 128), 256>>>(nullptr,  2, dec_bih);

    // Encoder recurrences (pre + post in one grid per step)
    for (int t = 0; t < Ss; t++)
        gru_step<<<dim3(Hh / 8, 2), 256>>>(0, t, pre_Whh, post_Whh, pre_bhh, post_bhh);

    // score_enc over all encoder outputs; decoder initial hidden
    score_kernel<<<dim3(Ss, 2), 64>>>(out_w);
    ench_kernel<<<Hh, 64>>>(enc_fc_w, enc_fc_b);

    // Decoder recurrence
    for (int t = 0; t < Tt; t++)
        gru_step<<<dim3(Hh / 8, 1), 256>>>(1, t, dec_Whh, dec_Whh, dec_bhh, dec_bhh);

    // Logits -> probabilities -> output
    hsc_kernel<<<Tt, 64>>>(out_w, out_b);
    probs_kernel<<<Bb * Tt, 256>>>(out);
}

// round 13
// speedup vs baseline: 1.6385x; 1.3042x over previous
#include <cuda_runtime.h>
#include <cuda_bf16.h>
#include <math.h>
#include <stdint.h>

// Problem dims
#define Bb   64
#define Ss   512
#define Tt   64
#define Hh   512
#define Dd   512
#define G3   1536          // 3*H
#define HB   (Hh*Bb)       // 32768, one hidden state in [j][b] layout
#define Vv   32000

// ---------------------------------------------------------------------------
// Scratch (device globals; no allocations allowed)
// ---------------------------------------------------------------------------
__device__ __align__(16) float g_gi[2][(size_t)Bb*Ss*G3];   // pre/post gate inputs [b][s][g]
__device__ __align__(16) float g_gid[(size_t)Bb*Tt*G3];     // decoder gate inputs  [b][t][g]
__device__ __align__(16) float g_hist[2][(size_t)(Ss+1)*HB];// encoder h history [t][j][b]
__device__ __align__(16) float g_dhist[(size_t)(Tt+1)*HB];  // decoder h history [t][j][b]
__device__ __align__(16) float g_score[Bb*2*Ss];            // score_enc [b][s2]
__device__ __align__(16) float g_hsc[Tt*Bb];                // decoder hidden scores [t][b]
__device__ int   g_dtok[Bb*Tt];                             // decoder input tokens

// bf16 operands for the gate-input GEMMs
__device__ __align__(16) __nv_bfloat16 g_emb_bf[(size_t)Vv*Dd];
__device__ __align__(16) __nv_bfloat16 g_w_bf[3][(size_t)G3*Dd];

// split-bf16 recurrence operands: Whh (static) and h (per-step ping-pong)
__device__ __align__(16) __nv_bfloat16 g_whh_hi[3][(size_t)G3*Hh];  // [gru 0,1,2=dec]
__device__ __align__(16) __nv_bfloat16 g_whh_lo[3][(size_t)G3*Hh];
__device__ __align__(16) __nv_bfloat16 g_hbf_hi[3][2][Bb*Hh];       // [gru][parity][b*512+k]
__device__ __align__(16) __nv_bfloat16 g_hbf_lo[3][2][Bb*Hh];

// ---------------------------------------------------------------------------
// init: zero h0 (fp32 + bf16 split) for both encoder GRUs
// ---------------------------------------------------------------------------
__global__ void init_kernel() {
    int i = blockIdx.x * blockDim.x + threadIdx.x;
    if (i < HB) {
        g_hist[0][i] = 0.f; g_hist[1][i] = 0.f;
        __nv_bfloat16 z = __float2bfloat16(0.f);
        g_hbf_hi[0][0][i] = z; g_hbf_lo[0][0][i] = z;
        g_hbf_hi[1][0][i] = z; g_hbf_lo[1][0][i] = z;
    }
}

// decoder tokens: [pre_seq[:, -1:], trg[:, :-1]]
__global__ void dectok_kernel(const int* __restrict__ pre_seq,
                              const int* __restrict__ trg) {
    int idx = blockIdx.x * blockDim.x + threadIdx.x;
    if (idx >= Bb * Tt) return;
    int b = idx >> 6, t = idx & 63;
    g_dtok[idx] = (t == 0) ? pre_seq[b * Ss + (Ss - 1)] : trg[b * Tt + t - 1];
}

// fp32 -> bf16 conversion. which: 0=emb, 1..3 = W[0..2]
__global__ void prep_kernel(const float* __restrict__ src, int which, int n) {
    int i = blockIdx.x * blockDim.x + threadIdx.x;
    if (i >= n) return;
    __nv_bfloat16* d = (which == 0) ? g_emb_bf : g_w_bf[which - 1];
    d[i] = __float2bfloat16(src[i]);
}

// fp32 -> (hi, lo) bf16 split of Whh. which: 0,1 = encoders, 2 = decoder
__global__ void prep_whh(const float* __restrict__ src, int which) {
    int i = blockIdx.x * blockDim.x + threadIdx.x;
    if (i >= G3 * Hh) return;
    float x = src[i];
    __nv_bfloat16 h = __float2bfloat16(x);
    g_whh_hi[which][i] = h;
    g_whh_lo[which][i] = __float2bfloat16(x - __bfloat162float(h));
}

// ---------------------------------------------------------------------------
// bf16 mma.sync m16n8k16 (HMMA path; compiles at compute_103 family target)
// ---------------------------------------------------------------------------
__device__ __forceinline__ void mma_bf16(float* d, const unsigned* a, const unsigned* b) {
    asm volatile(
        "mma.sync.aligned.m16n8k16.row.col.f32.bf16.bf16.f32 "
        "{%0,%1,%2,%3}, {%4,%5,%6,%7}, {%8,%9}, {%0,%1,%2,%3};"
        : "+f"(d[0]), "+f"(d[1]), "+f"(d[2]), "+f"(d[3])
        : "r"(a[0]), "r"(a[1]), "r"(a[2]), "r"(a[3]), "r"(b[0]), "r"(b[1]));
}

__device__ __forceinline__ float fsigmoid(float x) {
    return 1.f / (1.f + __expf(-x));
}

// ---------------------------------------------------------------------------
// Tensor-core fused gather-GEMM (bf16, m16n8k16) — R12-exact (measured win).
// C[m][n] = sum_k emb[token[m]][k] * W[n][k] + bias[n]
// ---------------------------------------------------------------------------
#define KP 40                      // row pitch in bf16 (20 words)
__global__ __launch_bounds__(256, 2) void gemm_gather_bf(
    const int* __restrict__ tokens_arg, int dst,
    const float* __restrict__ bias)
{
    __shared__ __align__(16) __nv_bfloat16 As[2][128 * KP];
    __shared__ __align__(16) __nv_bfloat16 Bs[2][128 * KP];

    int tid = threadIdx.x;
    const int* tokens = (dst == 2) ? g_dtok : tokens_arg;
    float* C = (dst == 0) ? g_gi[0] : (dst == 1) ? g_gi[1] : g_gid;
    const __nv_bfloat16* W = g_w_bf[dst];

    int m0 = blockIdx.x * 128;
    int n0 = blockIdx.y * 128;

    int row = tid >> 1;
    int seg = tid & 1;
    int tok = tokens[m0 + row];
    const __nv_bfloat16* arow = g_emb_bf + (size_t)tok * Dd + seg * 16;
    const __nv_bfloat16* brow = W + (size_t)(n0 + row) * Dd + seg * 16;
    int sdst = row * KP + seg * 16;

    int w = tid >> 5;
    int wm = (w >> 1) << 5;
    int wn = (w & 1) << 6;
    int lane = tid & 31;
    int grp = lane >> 2;
    int q   = lane & 3;

    float acc[2][8][4];
    #pragma unroll
    for (int mi = 0; mi < 2; mi++)
        #pragma unroll
        for (int ni = 0; ni < 8; ni++)
            #pragma unroll
            for (int r = 0; r < 4; r++) acc[mi][ni][r] = 0.f;

    uint4 pa0 = *(const uint4*)(arow);
    uint4 pa1 = *(const uint4*)(arow + 8);
    uint4 pb0 = *(const uint4*)(brow);
    uint4 pb1 = *(const uint4*)(brow + 8);

    for (int k0 = 0; k0 < Dd; k0 += 32) {
        int buf = (k0 >> 5) & 1;
        *(uint4*)&As[buf][sdst]     = pa0;
        *(uint4*)&As[buf][sdst + 8] = pa1;
        *(uint4*)&Bs[buf][sdst]     = pb0;
        *(uint4*)&Bs[buf][sdst + 8] = pb1;
        __syncthreads();

        if (k0 + 32 < Dd) {
            pa0 = *(const uint4*)(arow + k0 + 32);
            pa1 = *(const uint4*)(arow + k0 + 40);
            pb0 = *(const uint4*)(brow + k0 + 32);
            pb1 = *(const uint4*)(brow + k0 + 40);
        }

        const unsigned* Aw = (const unsigned*)As[buf];
        const unsigned* Bw = (const unsigned*)Bs[buf];
        #pragma unroll
        for (int ks = 0; ks < 2; ks++) {
            int kb = ks * 8;
            unsigned a[2][4], b[8][2];
            #pragma unroll
            for (int mi = 0; mi < 2; mi++) {
                int r0 = (wm + mi * 16 + grp) * 20;
                int r1 = (wm + mi * 16 + grp + 8) * 20;
                a[mi][0] = Aw[r0 + kb + q];
                a[mi][1] = Aw[r1 + kb + q];
                a[mi][2] = Aw[r0 + kb + q + 4];
                a[mi][3] = Aw[r1 + kb + q + 4];
            }
            #pragma unroll
            for (int ni = 0; ni < 8; ni++) {
                int rn = (wn + ni * 8 + grp) * 20;
                b[ni][0] = Bw[rn + kb + q];
                b[ni][1] = Bw[rn + kb + q + 4];
            }
            #pragma unroll
            for (int mi = 0; mi < 2; mi++)
                #pragma unroll
                for (int ni = 0; ni < 8; ni++)
                    mma_bf16(acc[mi][ni], a[mi], b[ni]);
        }
        __syncthreads();
    }

    #pragma unroll
    for (int mi = 0; mi < 2; mi++) {
        int mrow = m0 + wm + mi * 16 + grp;
        #pragma unroll
        for (int ni = 0; ni < 8; ni++) {
            int ncol = n0 + wn + ni * 8 + q * 2;
            float b0 = bias[ncol], b1 = bias[ncol + 1];
            *(float2*)&C[(size_t)mrow * G3 + ncol] =
                make_float2(acc[mi][ni][0] + b0, acc[mi][ni][1] + b1);
            *(float2*)&C[(size_t)(mrow + 8) * G3 + ncol] =
                make_float2(acc[mi][ni][2] + b0, acc[mi][ni][3] + b1);
        }
    }
}

// ---------------------------------------------------------------------------
// GRU step via bf16 HMMA (split hi/lo = fp32-accurate recurrence).
// gates[b][rr] = sum_k h[b][k] * Whh[row(rr)][k], rr = gate*16 + jj for the
// CTA's 16 j-columns; 3 passes (Whi*hhi + Whi*hlo + Wlo*hhi) in fp32 acc.
// A = h (M=64, row-major [b][k] bf16), B = Whh rows (col-major-in-k) — both
// contiguous in k; fragment maps identical to the verified gemm_gather_bf.
// K chunked 64, double-buffered, register prefetch. Fused GRU pointwise
// epilogue via a 64x50 smem gate buffer (all 3 gates in-CTA by construction).
// Grid (32 j-tiles, nGru), 256 threads. Writes h fp32 [j][b] + hbf hi/lo [b][k].
// ---------------------------------------------------------------------------
#define WKPW 36                    // stage row pitch in words (64 bf16 + pad)
#define BUFW (224 * WKPW)          // words per stage buffer (224 rows)
#define SGP  50                    // gate-buffer pitch (floats)
#define GRU_SMEM ((2 * BUFW) * 4 + Bb * SGP * 4)

__global__ __launch_bounds__(256) void gru_mma_step(
    int isDec, int t,
    const float* __restrict__ bhh0, const float* __restrict__ bhh1)
{
    extern __shared__ __align__(16) unsigned smn[];
    int gru = blockIdx.y;
    int which = isDec ? 2 : gru;
    const float* gi  = isDec ? g_gid : g_gi[gru];
    float* hist      = isDec ? g_dhist : g_hist[gru];
    const float* bhh = gru ? bhh1 : bhh0;
    int seq = isDec ? Tt : Ss;
    int rp = t & 1, wp = rp ^ 1;

    const __nv_bfloat16* hhi = g_hbf_hi[which][rp];
    const __nv_bfloat16* hlo = g_hbf_lo[which][rp];
    const __nv_bfloat16* whi = g_whh_hi[which];
    const __nv_bfloat16* wlo = g_whh_lo[which];

    int tid = threadIdx.x;
    int j0 = blockIdx.x * 16;

    // staging: 224 rows x 64 bf16 per chunk; thread owns 7 uint4 (fixed map)
    const __nv_bfloat16* srcp[7];
    unsigned dstw[7];
    #pragma unroll
    for (int i = 0; i < 7; i++) {
        int l = tid + i * 256;
        int row = l >> 3, col = l & 7;
        const __nv_bfloat16* base;
        if (row < 64)       base = hhi + row * Hh;                 // A hi (b=row)
        else if (row < 128) base = hlo + (row - 64) * Hh;          // A lo
        else {
            int rr = row - 128;
            int isLo = (rr >= 48); if (isLo) rr -= 48;
            int g = rr >> 4, jj = rr & 15;
            int wrow = g * Hh + j0 + jj;                           // gate row
            base = (isLo ? wlo : whi) + (size_t)wrow * Hh;
        }
        srcp[i] = base + col * 8;
        dstw[i] = row * WKPW + col * 4;
    }

    // warp decomposition: 8 warps = 4 m-frags x 2 n-halves (24 n each)
    int w = tid >> 5, lane = tid & 31;
    int wm = (w >> 1) << 4;            // 0,16,32,48
    int wn = (w & 1) * 24;             // 0 or 24
    int grp = lane >> 2, q = lane & 3;

    float acc[3][4];
    #pragma unroll
    for (int ni = 0; ni < 3; ni++)
        #pragma unroll
        for (int r = 0; r < 4; r++) acc[ni][r] = 0.f;

    uint4 pf[7];
    #pragma unroll
    for (int i = 0; i < 7; i++) pf[i] = *(const uint4*)(srcp[i]);

    for (int c = 0; c < 8; c++) {
        unsigned* buf = smn + (c & 1) * BUFW;
        #pragma unroll
        for (int i = 0; i < 7; i++) *(uint4*)(buf + dstw[i]) = pf[i];
        __syncthreads();
        if (c < 7) {
            #pragma unroll
            for (int i = 0; i < 7; i++)
                pf[i] = *(const uint4*)(srcp[i] + (c + 1) * 64);
        }
        const unsigned* A = buf;                 // rows 0..127 (hi/lo)
        const unsigned* B = buf + 128 * WKPW;    // rows 0..95 (hi/lo)
        #pragma unroll
        for (int p = 0; p < 3; p++) {
            int aoff = (p == 1) ? 64 * WKPW : 0;   // pass1: A = h_lo
            int boff = (p == 2) ? 48 * WKPW : 0;   // pass2: B = W_lo
            #pragma unroll
            for (int ks = 0; ks < 4; ks++) {
                int kb = ks * 8;
                unsigned a[4], bfr[3][2];
                int r0 = aoff + (wm + grp) * WKPW;
                int r1 = aoff + (wm + grp + 8) * WKPW;
                a[0] = A[r0 + kb + q];
                a[1] = A[r1 + kb + q];
                a[2] = A[r0 + kb + q + 4];
                a[3] = A[r1 + kb + q + 4];
                #pragma unroll
                for (int ni = 0; ni < 3; ni++) {
                    int rn = boff + (wn + ni * 8 + grp) * WKPW;
                    bfr[ni][0] = B[rn + kb + q];
                    bfr[ni][1] = B[rn + kb + q + 4];
                }
                #pragma unroll
                for (int ni = 0; ni < 3; ni++)
                    mma_bf16(acc[ni], a, bfr[ni]);
            }
        }
        __syncthreads();
    }

    // gates -> smem buffer sg[b][rr]
    float* sg = (float*)(smn + 2 * BUFW);
    #pragma unroll
    for (int ni = 0; ni < 3; ni++) {
        int n = wn + ni * 8 + q * 2;
        *(float2*)&sg[(wm + grp) * SGP + n]     = make_float2(acc[ni][0], acc[ni][1]);
        *(float2*)&sg[(wm + grp + 8) * SGP + n] = make_float2(acc[ni][2], acc[ni][3]);
    }
    __syncthreads();

    // fused GRU pointwise: 1024 items (b, jj), 4 per thread
    __nv_bfloat16* ohi = g_hbf_hi[which][wp];
    __nv_bfloat16* olo = g_hbf_lo[which][wp];
    #pragma unroll
    for (int it = 0; it < 4; it++) {
        int idx = tid + it * 256;
        int b = idx & 63, jj = idx >> 6;
        int j = j0 + jj;
        const float* g = gi + ((size_t)b * seq + t) * G3;
        float pr = g[j]        + sg[b * SGP + jj]      + bhh[j];
        float pz = g[Hh + j]   + sg[b * SGP + 16 + jj] + bhh[Hh + j];
        float hn = sg[b * SGP + 32 + jj] + bhh[2 * Hh + j];
        float r = fsigmoid(pr);
        float z = fsigmoid(pz);
        float nn = tanhf(g[2 * Hh + j] + r * hn);
        float hold = hist[(size_t)t * HB + j * Bb + b];
        float ho = (1.f - z) * nn + z * hold;
        hist[(size_t)(t + 1) * HB + j * Bb + b] = ho;
        __nv_bfloat16 hh = __float2bfloat16(ho);
        ohi[b * Hh + j] = hh;
        olo[b * Hh + j] = __float2bfloat16(ho - __bfloat162float(hh));
    }
}

// ---------------------------------------------------------------------------
// score_enc[b][gru*S + t] = sum_j relu(h_{t+1}[j][b]) * w_enc[j]
// ---------------------------------------------------------------------------
__global__ __launch_bounds__(64) void score_kernel(const float* __restrict__ out_w) {
    int t = blockIdx.x, gru = blockIdx.y, b = threadIdx.x;
    const float* hrow = g_hist[gru] + (size_t)(t + 1) * HB;
    float acc = 0.f;
    for (int j = 0; j < Hh; j++)
        acc += fmaxf(hrow[j * Bb + b], 0.f) * out_w[j];
    g_score[b * (2 * Ss) + gru * Ss + t] = acc;
}

// ---------------------------------------------------------------------------
// enc_hidden (decoder h0) = tanh(cat(pre_h, post_h) @ enc_fc_w^T + enc_fc_b)
// also emits the decoder's hbf hi/lo for the first mma step
// ---------------------------------------------------------------------------
__global__ __launch_bounds__(64) void ench_kernel(const float* __restrict__ enc_fc_w,
                                                  const float* __restrict__ enc_fc_b) {
    int i = blockIdx.x, b = threadIdx.x;
    const float* w = enc_fc_w + (size_t)i * (2 * Hh);
    const float* hp0 = g_hist[0] + (size_t)Ss * HB;
    const float* hp1 = g_hist[1] + (size_t)Ss * HB;
    float acc = enc_fc_b[i];
    for (int q = 0; q < Hh; q++) acc += hp0[q * Bb + b] * w[q];
    for (int q = 0; q < Hh; q++) acc += hp1[q * Bb + b] * w[Hh + q];
    float th = tanhf(acc);
    g_dhist[i * Bb + b] = th;
    __nv_bfloat16 hh = __float2bfloat16(th);
    g_hbf_hi[2][0][b * Hh + i] = hh;
    g_hbf_lo[2][0][b * Hh + i] = __float2bfloat16(th - __bfloat162float(hh));
}

// ---------------------------------------------------------------------------
// decoder hidden score: hsc[t][b] = relu(hdec_{t+1}[:,b]) . w_hid + out_b
// ---------------------------------------------------------------------------
__global__ __launch_bounds__(64) void hsc_kernel(const float* __restrict__ out_w,
                                                 const float* __restrict__ out_b) {
    int t = blockIdx.x, b = threadIdx.x;
    const float* hrow = g_dhist + (size_t)(t + 1) * HB;
    float acc = 0.f;
    for (int j = 0; j < Hh; j++)
        acc += fmaxf(hrow[j * Bb + b], 0.f) * out_w[Hh + j];
    g_hsc[t * Bb + b] = acc + out_b[0];
}

// ---------------------------------------------------------------------------
// probs: out_pre[b][t][s] = sigmoid(score[b][s] + hsc[t][b]); post analogous
// ---------------------------------------------------------------------------
__global__ __launch_bounds__(256) void probs_kernel(float* __restrict__ out) {
    int bt = blockIdx.x;
    int b = bt >> 6, t = bt & 63;
    float hs = g_hsc[t * Bb + b];
    const float* sc = g_score + b * (2 * Ss);
    float* out_pre  = out + (size_t)bt * Ss;
    float* out_post = out + (size_t)Bb * Tt * Ss + (size_t)bt * Ss;
    #pragma unroll
    for (int it = 0; it < 4; it++) {
        int s2 = it * 256 + threadIdx.x;
        float l = sc[s2] + hs;
        float p = 1.f / (1.f + expf(-l));
        if (s2 < Ss) out_pre[s2] = p;
        else         out_post[s2 - Ss] = p;
    }
}

// ---------------------------------------------------------------------------
// launch
// ---------------------------------------------------------------------------
extern "C" void kernel_launch(void* const* d_in, const int* in_sizes, int n_in,
                              void* d_out, int out_size) {
    const int*   pre_seq   = (const int*)  d_in[0];
    const int*   post_seq  = (const int*)  d_in[1];
    const int*   trg       = (const int*)  d_in[2];
    const float* emb       = (const float*)d_in[3];
    const float* pre_Wih   = (const float*)d_in[4];
    const float* pre_Whh   = (const float*)d_in[5];
    const float* pre_bih   = (const float*)d_in[6];
    const float* pre_bhh   = (const float*)d_in[7];
    const float* post_Wih  = (const float*)d_in[8];
    const float* post_Whh  = (const float*)d_in[9];
    const float* post_bih  = (const float*)d_in[10];
    const float* post_bhh  = (const float*)d_in[11];
    const float* enc_fc_w  = (const float*)d_in[12];
    const float* enc_fc_b  = (const float*)d_in[13];
    const float* dec_Wih   = (const float*)d_in[14];
    const float* dec_Whh   = (const float*)d_in[15];
    const float* dec_bih   = (const float*)d_in[16];
    const float* dec_bhh   = (const float*)d_in[17];
    const float* out_w     = (const float*)d_in[18];
    const float* out_b     = (const float*)d_in[19];
    float* out = (float*)d_out;

    cudaFuncSetAttribute(gru_mma_step,
                         cudaFuncAttributeMaxDynamicSharedMemorySize, GRU_SMEM);

    // h0, decoder tokens, bf16 conversions (gi operands + Whh hi/lo splits)
    init_kernel<<<128, 256>>>();
    dectok_kernel<<<16, 256>>>(pre_seq, trg);
    prep_kernel<<<(Vv * Dd + 255) / 256, 256>>>(emb, 0, Vv * Dd);
    prep_kernel<<<(G3 * Dd + 255) / 256, 256>>>(pre_Wih,  1, G3 * Dd);
    prep_kernel<<<(G3 * Dd + 255) / 256, 256>>>(post_Wih, 2, G3 * Dd);
    prep_kernel<<<(G3 * Dd + 255) / 256, 256>>>(dec_Wih,  3, G3 * Dd);
    prep_whh<<<(G3 * Hh + 255) / 256, 256>>>(pre_Whh,  0);
    prep_whh<<<(G3 * Hh + 255) / 256, 256>>>(post_Whh, 1);
    prep_whh<<<(G3 * Hh + 255) / 256, 256>>>(dec_Whh,  2);

    // Gate-input GEMMs (bf16 tensor-core mma, fused embedding gather)
    gemm_gather_bf<<<dim3(Bb * Ss / 128, G3 / 128), 256>>>(pre_seq,  0, pre_bih);
    gemm_gather_bf<<<dim3(Bb * Ss / 128, G3 / 128), 256>>>(post_seq, 1, post_bih);
    gemm_gather_bf<<<dim3(Bb * Tt / 128, G3 / 128), 256>>>(nullptr,  2, dec_bih);

    // Encoder recurrences: HMMA split-bf16 steps (pre + post in one grid)
    for (int t = 0; t < Ss; t++)
        gru_mma_step<<<dim3(Hh / 16, 2), 256, GRU_SMEM>>>(0, t, pre_bhh, post_bhh);

    // score_enc over all encoder outputs; decoder initial hidden (+ hbf)
    score_kernel<<<dim3(Ss, 2), 64>>>(out_w);
    ench_kernel<<<Hh, 64>>>(enc_fc_w, enc_fc_b);

    // Decoder recurrence
    for (int t = 0; t < Tt; t++)
        gru_mma_step<<<dim3(Hh / 16, 1), 256, GRU_SMEM>>>(1, t, dec_bhh, dec_bhh);

    // Logits -> probabilities -> output
    hsc_kernel<<<Tt, 64>>>(out_w, out_b);
    probs_kernel<<<Bb * Tt, 256>>>(out);
}

// round 15
// speedup vs baseline: 1.8429x; 1.1247x over previous
#include <cuda_runtime.h>
#include <cuda_bf16.h>
#include <math.h>
#include <stdint.h>

// Problem dims
#define Bb   64
#define Ss   512
#define Tt   64
#define Hh   512
#define Dd   512
#define G3   1536          // 3*H
#define HB   (Hh*Bb)       // 32768, one hidden state in [j][b] layout
#define Vv   32000

// ---------------------------------------------------------------------------
// Scratch (device globals; no allocations allowed)
// ---------------------------------------------------------------------------
__device__ __align__(16) float g_gi[2][(size_t)Bb*Ss*G3];   // pre/post gate inputs [b][s][g]
__device__ __align__(16) float g_gid[(size_t)Bb*Tt*G3];     // decoder gate inputs  [b][t][g]
__device__ __align__(16) float g_hist[2][(size_t)(Ss+1)*HB];// encoder h history [t][j][b]
__device__ __align__(16) float g_dhist[(size_t)(Tt+1)*HB];  // decoder h history [t][j][b]
__device__ __align__(16) float g_score[Bb*2*Ss];            // score_enc [b][s2]
__device__ __align__(16) float g_hsc[Tt*Bb];                // decoder hidden scores [t][b]
__device__ int   g_dtok[Bb*Tt];                             // decoder input tokens

// bf16 operands for the gate-input GEMMs
__device__ __align__(16) __nv_bfloat16 g_emb_bf[(size_t)Vv*Dd];
__device__ __align__(16) __nv_bfloat16 g_w_bf[3][(size_t)G3*Dd];

// split-bf16 recurrence operands: Whh (static) and h (per-step ping-pong)
__device__ __align__(16) __nv_bfloat16 g_whh_hi[3][(size_t)G3*Hh];  // [gru 0,1,2=dec]
__device__ __align__(16) __nv_bfloat16 g_whh_lo[3][(size_t)G3*Hh];
__device__ __align__(16) __nv_bfloat16 g_hbf_hi[3][2][Bb*Hh];       // [gru][parity][b*512+k]
__device__ __align__(16) __nv_bfloat16 g_hbf_lo[3][2][Bb*Hh];

// ---------------------------------------------------------------------------
// init: zero h0 (fp32 + bf16 split) for both encoder GRUs
// ---------------------------------------------------------------------------
__global__ void init_kernel() {
    int i = blockIdx.x * blockDim.x + threadIdx.x;
    if (i < HB) {
        g_hist[0][i] = 0.f; g_hist[1][i] = 0.f;
        __nv_bfloat16 z = __float2bfloat16(0.f);
        g_hbf_hi[0][0][i] = z; g_hbf_lo[0][0][i] = z;
        g_hbf_hi[1][0][i] = z; g_hbf_lo[1][0][i] = z;
    }
}

// decoder tokens: [pre_seq[:, -1:], trg[:, :-1]]
__global__ void dectok_kernel(const int* __restrict__ pre_seq,
                              const int* __restrict__ trg) {
    int idx = blockIdx.x * blockDim.x + threadIdx.x;
    if (idx >= Bb * Tt) return;
    int b = idx >> 6, t = idx & 63;
    g_dtok[idx] = (t == 0) ? pre_seq[b * Ss + (Ss - 1)] : trg[b * Tt + t - 1];
}

// fp32 -> bf16 conversion. which: 0=emb, 1..3 = W[0..2]
__global__ void prep_kernel(const float* __restrict__ src, int which, int n) {
    int i = blockIdx.x * blockDim.x + threadIdx.x;
    if (i >= n) return;
    __nv_bfloat16* d = (which == 0) ? g_emb_bf : g_w_bf[which - 1];
    d[i] = __float2bfloat16(src[i]);
}

// fp32 -> (hi, lo) bf16 split of Whh. which: 0,1 = encoders, 2 = decoder
__global__ void prep_whh(const float* __restrict__ src, int which) {
    int i = blockIdx.x * blockDim.x + threadIdx.x;
    if (i >= G3 * Hh) return;
    float x = src[i];
    __nv_bfloat16 h = __float2bfloat16(x);
    g_whh_hi[which][i] = h;
    g_whh_lo[which][i] = __float2bfloat16(x - __bfloat162float(h));
}

// ---------------------------------------------------------------------------
// bf16 mma.sync m16n8k16 (HMMA path; compiles at compute_103 family target)
// ---------------------------------------------------------------------------
__device__ __forceinline__ void mma_bf16(float* d, const unsigned* a, const unsigned* b) {
    asm volatile(
        "mma.sync.aligned.m16n8k16.row.col.f32.bf16.bf16.f32 "
        "{%0,%1,%2,%3}, {%4,%5,%6,%7}, {%8,%9}, {%0,%1,%2,%3};"
        : "+f"(d[0]), "+f"(d[1]), "+f"(d[2]), "+f"(d[3])
        : "r"(a[0]), "r"(a[1]), "r"(a[2]), "r"(a[3]), "r"(b[0]), "r"(b[1]));
}

__device__ __forceinline__ float fsigmoid(float x) {
    return 1.f / (1.f + __expf(-x));
}

// ---------------------------------------------------------------------------
// Fused step kernel. Per launch (grid x = recCnt + 24, y = nGru):
//  bx <  recCnt : GRU recurrence for step t (R13-exact HMMA split-bf16 path)
//  bx >= recCnt : GEMM CTAs computing gi[:, t+1, n0:n0+64) so the gate GEMM
//                 rides the otherwise-idle SMs of every step launch.
//                 (prologue: recCnt=0, t=-1 -> computes gi[:,0,:])
// GEMM branch: C[b][n] = sum_k emb[tok[b][t+1]][k] * Wih[n][k] + bih[n],
// M=64, N=64, K=512; R12-verified fragment/staging maps (2 uint4/thread!).
// ---------------------------------------------------------------------------
#define WKPW 36                    // rec stage row pitch in words (64 bf16 + pad)
#define BUFW (224 * WKPW)          // words per rec stage buffer (224 rows)
#define SGP  50                    // gate-buffer pitch (floats)
#define GRU_SMEM ((2 * BUFW) * 4 + Bb * SGP * 4)
#define KP 40                      // gemm stage row pitch in bf16 (20 words)

__global__ __launch_bounds__(256) void gru_mma_step(
    int isDec, int t, int recCnt,
    const float* __restrict__ bhh0, const float* __restrict__ bhh1,
    const float* __restrict__ bih0, const float* __restrict__ bih1,
    const int* __restrict__ tok0, const int* __restrict__ tok1)
{
    extern __shared__ __align__(16) unsigned smn[];
    int gru = blockIdx.y;
    int which = isDec ? 2 : gru;
    int seq = isDec ? Tt : Ss;
    int tid = threadIdx.x;
    int w = tid >> 5, lane = tid & 31;
    int grp = lane >> 2, q = lane & 3;

    if ((int)blockIdx.x >= recCnt) {
        // ================= GEMM branch: gi[:, t+1, n0..n0+64) =================
        int tn = t + 1;
        if (tn >= seq) return;
        int gx = blockIdx.x - recCnt;
        int n0 = gx * 64;
        const int* toks = isDec ? g_dtok : (gru ? tok1 : tok0);
        const __nv_bfloat16* Wg = g_w_bf[which];
        const float* bih = gru ? bih1 : bih0;
        float* giw = isDec ? g_gid : g_gi[gru];

        __nv_bfloat16* St = (__nv_bfloat16*)smn;   // 2 x 128*KP bf16 (20KB)

        // staging: 128 rows (64 A=emb, 64 B=Wih) x 32 k; thread = 2 uint4
        // (seg selects the 16-bf16 half of the 32-wide row; both uint4 of
        //  that half are written — R12-verified pattern)
        int row = tid >> 1, seg = tid & 1;
        const __nv_bfloat16* srcrow;
        if (row < 64) {
            int tok = toks[row * seq + tn];
            srcrow = g_emb_bf + (size_t)tok * Dd;
        } else {
            srcrow = Wg + (size_t)(n0 + row - 64) * Dd;
        }
        srcrow += seg * 16;
        int sdst = row * KP + seg * 16;

        int wm = (w >> 2) << 5;        // 0 or 32
        int wn = (w & 3) << 4;         // 0,16,32,48

        float acc[2][2][4];
        #pragma unroll
        for (int mi = 0; mi < 2; mi++)
            #pragma unroll
            for (int ni = 0; ni < 2; ni++)
                #pragma unroll
                for (int r = 0; r < 4; r++) acc[mi][ni][r] = 0.f;

        uint4 pf0 = *(const uint4*)srcrow;
        uint4 pf1 = *(const uint4*)(srcrow + 8);
        for (int k0 = 0; k0 < Dd; k0 += 32) {
            __nv_bfloat16* buf = St + ((k0 >> 5) & 1) * (128 * KP);
            *(uint4*)&buf[sdst]     = pf0;
            *(uint4*)&buf[sdst + 8] = pf1;
            __syncthreads();
            if (k0 + 32 < Dd) {
                pf0 = *(const uint4*)(srcrow + k0 + 32);
                pf1 = *(const uint4*)(srcrow + k0 + 40);
            }
            const unsigned* Sw = (const unsigned*)buf;
            #pragma unroll
            for (int ks = 0; ks < 2; ks++) {
                int kb = ks * 8;
                unsigned a[2][4], bfr[2][2];
                #pragma unroll
                for (int mi = 0; mi < 2; mi++) {
                    int r0 = (wm + mi * 16 + grp) * 20;
                    int r1 = r0 + 8 * 20;
                    a[mi][0] = Sw[r0 + kb + q];
                    a[mi][1] = Sw[r1 + kb + q];
                    a[mi][2] = Sw[r0 + kb + q + 4];
                    a[mi][3] = Sw[r1 + kb + q + 4];
                }
                #pragma unroll
                for (int ni = 0; ni < 2; ni++) {
                    int rn = (64 + wn + ni * 8 + grp) * 20;
                    bfr[ni][0] = Sw[rn + kb + q];
                    bfr[ni][1] = Sw[rn + kb + q + 4];
                }
                #pragma unroll
                for (int mi = 0; mi < 2; mi++)
                    #pragma unroll
                    for (int ni = 0; ni < 2; ni++)
                        mma_bf16(acc[mi][ni], a[mi], bfr[ni]);
            }
            __syncthreads();
        }

        #pragma unroll
        for (int mi = 0; mi < 2; mi++) {
            int b0r = wm + mi * 16 + grp;          // batch row
            #pragma unroll
            for (int ni = 0; ni < 2; ni++) {
                int ncol = n0 + wn + ni * 8 + q * 2;
                float bb0 = bih[ncol], bb1 = bih[ncol + 1];
                float* g0 = giw + ((size_t)b0r * seq + tn) * G3;
                float* g1 = giw + ((size_t)(b0r + 8) * seq + tn) * G3;
                *(float2*)&g0[ncol] = make_float2(acc[mi][ni][0] + bb0,
                                                  acc[mi][ni][1] + bb1);
                *(float2*)&g1[ncol] = make_float2(acc[mi][ni][2] + bb0,
                                                  acc[mi][ni][3] + bb1);
            }
        }
        return;
    }

    // ================= Recurrence branch (R13-exact) =================
    const float* gi  = isDec ? g_gid : g_gi[gru];
    float* hist      = isDec ? g_dhist : g_hist[gru];
    const float* bhh = gru ? bhh1 : bhh0;
    int rp = t & 1, wp = rp ^ 1;

    const __nv_bfloat16* hhi = g_hbf_hi[which][rp];
    const __nv_bfloat16* hlo = g_hbf_lo[which][rp];
    const __nv_bfloat16* whi = g_whh_hi[which];
    const __nv_bfloat16* wlo = g_whh_lo[which];

    int j0 = blockIdx.x * 16;

    // staging: 224 rows x 64 bf16 per chunk; thread owns 7 uint4 (fixed map)
    const __nv_bfloat16* srcp[7];
    unsigned dstw[7];
    #pragma unroll
    for (int i = 0; i < 7; i++) {
        int l = tid + i * 256;
        int row = l >> 3, col = l & 7;
        const __nv_bfloat16* base;
        if (row < 64)       base = hhi + row * Hh;                 // A hi (b=row)
        else if (row < 128) base = hlo + (row - 64) * Hh;          // A lo
        else {
            int rr = row - 128;
            int isLo = (rr >= 48); if (isLo) rr -= 48;
            int g = rr >> 4, jj = rr & 15;
            int wrow = g * Hh + j0 + jj;                           // gate row
            base = (isLo ? wlo : whi) + (size_t)wrow * Hh;
        }
        srcp[i] = base + col * 8;
        dstw[i] = row * WKPW + col * 4;
    }

    // warp decomposition: 8 warps = 4 m-frags x 2 n-halves (24 n each)
    int wm = (w >> 1) << 4;            // 0,16,32,48
    int wn = (w & 1) * 24;             // 0 or 24

    float acc[3][4];
    #pragma unroll
    for (int ni = 0; ni < 3; ni++)
        #pragma unroll
        for (int r = 0; r < 4; r++) acc[ni][r] = 0.f;

    uint4 pf[7];
    #pragma unroll
    for (int i = 0; i < 7; i++) pf[i] = *(const uint4*)(srcp[i]);

    for (int c = 0; c < 8; c++) {
        unsigned* buf = smn + (c & 1) * BUFW;
        #pragma unroll
        for (int i = 0; i < 7; i++) *(uint4*)(buf + dstw[i]) = pf[i];
        __syncthreads();
        if (c < 7) {
            #pragma unroll
            for (int i = 0; i < 7; i++)
                pf[i] = *(const uint4*)(srcp[i] + (c + 1) * 64);
        }
        const unsigned* A = buf;                 // rows 0..127 (hi/lo)
        const unsigned* B = buf + 128 * WKPW;    // rows 0..95 (hi/lo)
        #pragma unroll
        for (int p = 0; p < 3; p++) {
            int aoff = (p == 1) ? 64 * WKPW : 0;   // pass1: A = h_lo
            int boff = (p == 2) ? 48 * WKPW : 0;   // pass2: B = W_lo
            #pragma unroll
            for (int ks = 0; ks < 4; ks++) {
                int kb = ks * 8;
                unsigned a[4], bfr[3][2];
                int r0 = aoff + (wm + grp) * WKPW;
                int r1 = aoff + (wm + grp + 8) * WKPW;
                a[0] = A[r0 + kb + q];
                a[1] = A[r1 + kb + q];
                a[2] = A[r0 + kb + q + 4];
                a[3] = A[r1 + kb + q + 4];
                #pragma unroll
                for (int ni = 0; ni < 3; ni++) {
                    int rn = boff + (wn + ni * 8 + grp) * WKPW;
                    bfr[ni][0] = B[rn + kb + q];
                    bfr[ni][1] = B[rn + kb + q + 4];
                }
                #pragma unroll
                for (int ni = 0; ni < 3; ni++)
                    mma_bf16(acc[ni], a, bfr[ni]);
            }
        }
        __syncthreads();
    }

    // gates -> smem buffer sg[b][rr]
    float* sg = (float*)(smn + 2 * BUFW);
    #pragma unroll
    for (int ni = 0; ni < 3; ni++) {
        int n = wn + ni * 8 + q * 2;
        *(float2*)&sg[(wm + grp) * SGP + n]     = make_float2(acc[ni][0], acc[ni][1]);
        *(float2*)&sg[(wm + grp + 8) * SGP + n] = make_float2(acc[ni][2], acc[ni][3]);
    }
    __syncthreads();

    // fused GRU pointwise: 1024 items (b, jj), 4 per thread
    __nv_bfloat16* ohi = g_hbf_hi[which][wp];
    __nv_bfloat16* olo = g_hbf_lo[which][wp];
    #pragma unroll
    for (int it = 0; it < 4; it++) {
        int idx = tid + it * 256;
        int b = idx & 63, jj = idx >> 6;
        int j = j0 + jj;
        const float* g = gi + ((size_t)b * seq + t) * G3;
        float pr = g[j]        + sg[b * SGP + jj]      + bhh[j];
        float pz = g[Hh + j]   + sg[b * SGP + 16 + jj] + bhh[Hh + j];
        float hn = sg[b * SGP + 32 + jj] + bhh[2 * Hh + j];
        float r = fsigmoid(pr);
        float z = fsigmoid(pz);
        float nn = tanhf(g[2 * Hh + j] + r * hn);
        float hold = hist[(size_t)t * HB + j * Bb + b];
        float ho = (1.f - z) * nn + z * hold;
        hist[(size_t)(t + 1) * HB + j * Bb + b] = ho;
        __nv_bfloat16 hh = __float2bfloat16(ho);
        ohi[b * Hh + j] = hh;
        olo[b * Hh + j] = __float2bfloat16(ho - __bfloat162float(hh));
    }
}

// ---------------------------------------------------------------------------
// score_enc[b][gru*S + t] = sum_j relu(h_{t+1}[j][b]) * w_enc[j]
// ---------------------------------------------------------------------------
__global__ __launch_bounds__(64) void score_kernel(const float* __restrict__ out_w) {
    int t = blockIdx.x, gru = blockIdx.y, b = threadIdx.x;
    const float* hrow = g_hist[gru] + (size_t)(t + 1) * HB;
    float acc = 0.f;
    for (int j = 0; j < Hh; j++)
        acc += fmaxf(hrow[j * Bb + b], 0.f) * out_w[j];
    g_score[b * (2 * Ss) + gru * Ss + t] = acc;
}

// ---------------------------------------------------------------------------
// enc_hidden (decoder h0) = tanh(cat(pre_h, post_h) @ enc_fc_w^T + enc_fc_b)
// also emits the decoder's hbf hi/lo for the first mma step
// ---------------------------------------------------------------------------
__global__ __launch_bounds__(64) void ench_kernel(const float* __restrict__ enc_fc_w,
                                                  const float* __restrict__ enc_fc_b) {
    int i = blockIdx.x, b = threadIdx.x;
    const float* w = enc_fc_w + (size_t)i * (2 * Hh);
    const float* hp0 = g_hist[0] + (size_t)Ss * HB;
    const float* hp1 = g_hist[1] + (size_t)Ss * HB;
    float acc = enc_fc_b[i];
    for (int q = 0; q < Hh; q++) acc += hp0[q * Bb + b] * w[q];
    for (int q = 0; q < Hh; q++) acc += hp1[q * Bb + b] * w[Hh + q];
    float th = tanhf(acc);
    g_dhist[i * Bb + b] = th;
    __nv_bfloat16 hh = __float2bfloat16(th);
    g_hbf_hi[2][0][b * Hh + i] = hh;
    g_hbf_lo[2][0][b * Hh + i] = __float2bfloat16(th - __bfloat162float(hh));
}

// ---------------------------------------------------------------------------
// decoder hidden score: hsc[t][b] = relu(hdec_{t+1}[:,b]) . w_hid + out_b
// ---------------------------------------------------------------------------
__global__ __launch_bounds__(64) void hsc_kernel(const float* __restrict__ out_w,
                                                 const float* __restrict__ out_b) {
    int t = blockIdx.x, b = threadIdx.x;
    const float* hrow = g_dhist + (size_t)(t + 1) * HB;
    float acc = 0.f;
    for (int j = 0; j < Hh; j++)
        acc += fmaxf(hrow[j * Bb + b], 0.f) * out_w[Hh + j];
    g_hsc[t * Bb + b] = acc + out_b[0];
}

// ---------------------------------------------------------------------------
// probs: out_pre[b][t][s] = sigmoid(score[b][s] + hsc[t][b]); post analogous
// ---------------------------------------------------------------------------
__global__ __launch_bounds__(256) void probs_kernel(float* __restrict__ out) {
    int bt = blockIdx.x;
    int b = bt >> 6, t = bt & 63;
    float hs = g_hsc[t * Bb + b];
    const float* sc = g_score + b * (2 * Ss);
    float* out_pre  = out + (size_t)bt * Ss;
    float* out_post = out + (size_t)Bb * Tt * Ss + (size_t)bt * Ss;
    #pragma unroll
    for (int it = 0; it < 4; it++) {
        int s2 = it * 256 + threadIdx.x;
        float l = sc[s2] + hs;
        float p = 1.f / (1.f + expf(-l));
        if (s2 < Ss) out_pre[s2] = p;
        else         out_post[s2 - Ss] = p;
    }
}

// ---------------------------------------------------------------------------
// launch
// ---------------------------------------------------------------------------
extern "C" void kernel_launch(void* const* d_in, const int* in_sizes, int n_in,
                              void* d_out, int out_size) {
    const int*   pre_seq   = (const int*)  d_in[0];
    const int*   post_seq  = (const int*)  d_in[1];
    const int*   trg       = (const int*)  d_in[2];
    const float* emb       = (const float*)d_in[3];
    const float* pre_Wih   = (const float*)d_in[4];
    const float* pre_Whh   = (const float*)d_in[5];
    const float* pre_bih   = (const float*)d_in[6];
    const float* pre_bhh   = (const float*)d_in[7];
    const float* post_Wih  = (const float*)d_in[8];
    const float* post_Whh  = (const float*)d_in[9];
    const float* post_bih  = (const float*)d_in[10];
    const float* post_bhh  = (const float*)d_in[11];
    const float* enc_fc_w  = (const float*)d_in[12];
    const float* enc_fc_b  = (const float*)d_in[13];
    const float* dec_Wih   = (const float*)d_in[14];
    const float* dec_Whh   = (const float*)d_in[15];
    const float* dec_bih   = (const float*)d_in[16];
    const float* dec_bhh   = (const float*)d_in[17];
    const float* out_w     = (const float*)d_in[18];
    const float* out_b     = (const float*)d_in[19];
    float* out = (float*)d_out;

    cudaFuncSetAttribute(gru_mma_step,
                         cudaFuncAttributeMaxDynamicSharedMemorySize, GRU_SMEM);

    // h0, decoder tokens, bf16 conversions (gi operands + Whh hi/lo splits)
    init_kernel<<<128, 256>>>();
    dectok_kernel<<<16, 256>>>(pre_seq, trg);
    prep_kernel<<<(Vv * Dd + 255) / 256, 256>>>(emb, 0, Vv * Dd);
    prep_kernel<<<(G3 * Dd + 255) / 256, 256>>>(pre_Wih,  1, G3 * Dd);
    prep_kernel<<<(G3 * Dd + 255) / 256, 256>>>(post_Wih, 2, G3 * Dd);
    prep_kernel<<<(G3 * Dd + 255) / 256, 256>>>(dec_Wih,  3, G3 * Dd);
    prep_whh<<<(G3 * Hh + 255) / 256, 256>>>(pre_Whh,  0);
    prep_whh<<<(G3 * Hh + 255) / 256, 256>>>(post_Whh, 1);
    prep_whh<<<(G3 * Hh + 255) / 256, 256>>>(dec_Whh,  2);

    // Prologues: gi[:,0,:] for both encoders and the decoder (GEMM CTAs only)
    gru_mma_step<<<dim3(24, 2), 256, GRU_SMEM>>>(0, -1, 0,
        pre_bhh, post_bhh, pre_bih, post_bih, pre_seq, post_seq);
    gru_mma_step<<<dim3(24, 1), 256, GRU_SMEM>>>(1, -1, 0,
        dec_bhh, dec_bhh, dec_bih, dec_bih, nullptr, nullptr);

    // Encoder recurrences; each step launch also carries the GEMM CTAs
    // computing gi[:, t+1, :] on the otherwise-idle SMs
    for (int t = 0; t < Ss; t++)
        gru_mma_step<<<dim3(32 + 24, 2), 256, GRU_SMEM>>>(0, t, 32,
            pre_bhh, post_bhh, pre_bih, post_bih, pre_seq, post_seq);

    // score_enc over all encoder outputs; decoder initial hidden (+ hbf)
    score_kernel<<<dim3(Ss, 2), 64>>>(out_w);
    ench_kernel<<<Hh, 64>>>(enc_fc_w, enc_fc_b);

    // Decoder recurrence (same fused structure)
    for (int t = 0; t < Tt; t++)
        gru_mma_step<<<dim3(32 + 24, 1), 256, GRU_SMEM>>>(1, t, 32,
            dec_bhh, dec_bhh, dec_bih, dec_bih, nullptr, nullptr);

    // Logits -> probabilities -> output
    hsc_kernel<<<Tt, 64>>>(out_w, out_b);
    probs_kernel<<<Bb * Tt, 256>>>(out);
}

// round 16
// speedup vs baseline: 1.8826x; 1.0215x over previous
#include <cuda_runtime.h>
#include <cuda_bf16.h>
#include <math.h>
#include <stdint.h>

// Problem dims
#define Bb   64
#define Ss   512
#define Tt   64
#define Hh   512
#define Dd   512
#define G3   1536          // 3*H
#define HB   (Hh*Bb)       // 32768, one hidden state in [j][b] layout
#define Vv   32000

// ---------------------------------------------------------------------------
// Scratch (device globals; no allocations allowed)
// ---------------------------------------------------------------------------
__device__ __align__(16) float g_gi[2][(size_t)Bb*Ss*G3];   // pre/post gate inputs [b][s][g]
__device__ __align__(16) float g_gid[(size_t)Bb*Tt*G3];     // decoder gate inputs  [b][t][g]
__device__ __align__(16) float g_hist[2][(size_t)(Ss+1)*HB];// encoder h history [t][j][b]
__device__ __align__(16) float g_dhist[(size_t)(Tt+1)*HB];  // decoder h history [t][j][b]
__device__ __align__(16) float g_score[Bb*2*Ss];            // score_enc [b][s2]
__device__ __align__(16) float g_hsc[Tt*Bb];                // decoder hidden scores [t][b]
__device__ int   g_dtok[Bb*Tt];                             // decoder input tokens

// bf16 operands for the gate-input GEMMs
__device__ __align__(16) __nv_bfloat16 g_emb_bf[(size_t)Vv*Dd];
__device__ __align__(16) __nv_bfloat16 g_w_bf[3][(size_t)G3*Dd];

// split-bf16 recurrence operands: Whh (static) and h (per-step ping-pong)
__device__ __align__(16) __nv_bfloat16 g_whh_hi[3][(size_t)G3*Hh];  // [gru 0,1,2=dec]
__device__ __align__(16) __nv_bfloat16 g_whh_lo[3][(size_t)G3*Hh];
__device__ __align__(16) __nv_bfloat16 g_hbf_hi[3][2][Bb*Hh];       // [gru][parity][b*512+k]
__device__ __align__(16) __nv_bfloat16 g_hbf_lo[3][2][Bb*Hh];

// ---------------------------------------------------------------------------
// init: zero h0 (fp32 + bf16 split) for both encoder GRUs
// ---------------------------------------------------------------------------
__global__ void init_kernel() {
    int i = blockIdx.x * blockDim.x + threadIdx.x;
    if (i < HB) {
        g_hist[0][i] = 0.f; g_hist[1][i] = 0.f;
        __nv_bfloat16 z = __float2bfloat16(0.f);
        g_hbf_hi[0][0][i] = z; g_hbf_lo[0][0][i] = z;
        g_hbf_hi[1][0][i] = z; g_hbf_lo[1][0][i] = z;
    }
}

// decoder tokens: [pre_seq[:, -1:], trg[:, :-1]]
__global__ void dectok_kernel(const int* __restrict__ pre_seq,
                              const int* __restrict__ trg) {
    int idx = blockIdx.x * blockDim.x + threadIdx.x;
    if (idx >= Bb * Tt) return;
    int b = idx >> 6, t = idx & 63;
    g_dtok[idx] = (t == 0) ? pre_seq[b * Ss + (Ss - 1)] : trg[b * Tt + t - 1];
}

// fp32 -> bf16 conversion. which: 0=emb, 1..3 = W[0..2]
__global__ void prep_kernel(const float* __restrict__ src, int which, int n) {
    int i = blockIdx.x * blockDim.x + threadIdx.x;
    if (i >= n) return;
    __nv_bfloat16* d = (which == 0) ? g_emb_bf : g_w_bf[which - 1];
    d[i] = __float2bfloat16(src[i]);
}

// fp32 -> (hi, lo) bf16 split of Whh. which: 0,1 = encoders, 2 = decoder
__global__ void prep_whh(const float* __restrict__ src, int which) {
    int i = blockIdx.x * blockDim.x + threadIdx.x;
    if (i >= G3 * Hh) return;
    float x = src[i];
    __nv_bfloat16 h = __float2bfloat16(x);
    g_whh_hi[which][i] = h;
    g_whh_lo[which][i] = __float2bfloat16(x - __bfloat162float(h));
}

// ---------------------------------------------------------------------------
// bf16 mma.sync m16n8k16 (HMMA path; compiles at compute_103 family target)
// ---------------------------------------------------------------------------
__device__ __forceinline__ void mma_bf16(float* d, const unsigned* a, const unsigned* b) {
    asm volatile(
        "mma.sync.aligned.m16n8k16.row.col.f32.bf16.bf16.f32 "
        "{%0,%1,%2,%3}, {%4,%5,%6,%7}, {%8,%9}, {%0,%1,%2,%3};"
        : "+f"(d[0]), "+f"(d[1]), "+f"(d[2]), "+f"(d[3])
        : "r"(a[0]), "r"(a[1]), "r"(a[2]), "r"(a[3]), "r"(b[0]), "r"(b[1]));
}

__device__ __forceinline__ float fsigmoid(float x) {
    return 1.f / (1.f + __expf(-x));
}

// ---------------------------------------------------------------------------
// Fused step kernel. Per launch (grid x = recCnt + 12, y = nGru):
//  bx <  recCnt : GRU recurrence for step t (R13-exact HMMA split-bf16 path)
//  bx >= recCnt : GEMM CTAs computing gi[:, t+1, n0:n0+128) so the gate GEMM
//                 rides the otherwise-idle SMs of every step launch.
//                 (prologue: recCnt=0, t=-1 -> computes gi[:,0,:])
// GEMM branch (rebalanced R16): M=64, N=128, K=512 chunked 64 — same chunk
// shape/pitch/fragment maps as the recurrence branch, so both CTA kinds have
// matched duration (256 vs 288 mma/warp) and latency-hiding depth.
// ---------------------------------------------------------------------------
#define WKPW 36                    // stage row pitch in words (64 bf16 + pad)
#define BUFW (224 * WKPW)          // words per stage buffer (224 rows)
#define SGP  50                    // gate-buffer pitch (floats)
#define GRU_SMEM ((2 * BUFW) * 4 + Bb * SGP * 4)

__global__ __launch_bounds__(256) void gru_mma_step(
    int isDec, int t, int recCnt,
    const float* __restrict__ bhh0, const float* __restrict__ bhh1,
    const float* __restrict__ bih0, const float* __restrict__ bih1,
    const int* __restrict__ tok0, const int* __restrict__ tok1)
{
    extern __shared__ __align__(16) unsigned smn[];
    int gru = blockIdx.y;
    int which = isDec ? 2 : gru;
    int seq = isDec ? Tt : Ss;
    int tid = threadIdx.x;
    int w = tid >> 5, lane = tid & 31;
    int grp = lane >> 2, q = lane & 3;

    if ((int)blockIdx.x >= recCnt) {
        // ============ GEMM branch: gi[:, t+1, n0..n0+128), K chunked 64 ============
        int tn = t + 1;
        if (tn >= seq) return;
        int gx = blockIdx.x - recCnt;
        int n0 = gx * 128;
        const int* toks = isDec ? g_dtok : (gru ? tok1 : tok0);
        const __nv_bfloat16* Wg = g_w_bf[which];
        const float* bih = gru ? bih1 : bih0;
        float* giw = isDec ? g_gid : g_gi[gru];

        // staging: 192 rows (64 A=emb, 128 B=Wih) x 64 bf16; 6 uint4/thread
        const __nv_bfloat16* srcp[6];
        unsigned dstw[6];
        #pragma unroll
        for (int i = 0; i < 6; i++) {
            int l = tid + i * 256;
            int row = l >> 3, col = l & 7;
            const __nv_bfloat16* base;
            if (row < 64) {
                int tok = toks[row * seq + tn];
                base = g_emb_bf + (size_t)tok * Dd;
            } else {
                base = Wg + (size_t)(n0 + row - 64) * Dd;
            }
            srcp[i] = base + col * 8;
            dstw[i] = row * WKPW + col * 4;
        }

        int wm = (w >> 2) << 5;        // 0 or 32 (batch)
        int wn = (w & 3) << 5;         // 0,32,64,96 (n within 128)

        float acc[2][4][4];
        #pragma unroll
        for (int mi = 0; mi < 2; mi++)
            #pragma unroll
            for (int ni = 0; ni < 4; ni++)
                #pragma unroll
                for (int r = 0; r < 4; r++) acc[mi][ni][r] = 0.f;

        uint4 pf[6];
        #pragma unroll
        for (int i = 0; i < 6; i++) pf[i] = *(const uint4*)(srcp[i]);

        for (int c = 0; c < 8; c++) {
            unsigned* buf = smn + (c & 1) * BUFW;
            #pragma unroll
            for (int i = 0; i < 6; i++) *(uint4*)(buf + dstw[i]) = pf[i];
            __syncthreads();
            if (c < 7) {
                #pragma unroll
                for (int i = 0; i < 6; i++)
                    pf[i] = *(const uint4*)(srcp[i] + (c + 1) * 64);
            }
            const unsigned* A = buf;                // rows 0..63 (batch)
            const unsigned* B = buf + 64 * WKPW;    // rows 0..127 (n)
            #pragma unroll
            for (int ks = 0; ks < 4; ks++) {
                int kb = ks * 8;
                unsigned a[2][4], bfr[4][2];
                #pragma unroll
                for (int mi = 0; mi < 2; mi++) {
                    int r0 = (wm + mi * 16 + grp) * WKPW;
                    int r1 = r0 + 8 * WKPW;
                    a[mi][0] = A[r0 + kb + q];
                    a[mi][1] = A[r1 + kb + q];
                    a[mi][2] = A[r0 + kb + q + 4];
                    a[mi][3] = A[r1 + kb + q + 4];
                }
                #pragma unroll
                for (int ni = 0; ni < 4; ni++) {
                    int rn = (wn + ni * 8 + grp) * WKPW;
                    bfr[ni][0] = B[rn + kb + q];
                    bfr[ni][1] = B[rn + kb + q + 4];
                }
                #pragma unroll
                for (int mi = 0; mi < 2; mi++)
                    #pragma unroll
                    for (int ni = 0; ni < 4; ni++)
                        mma_bf16(acc[mi][ni], a[mi], bfr[ni]);
            }
            __syncthreads();
        }

        #pragma unroll
        for (int mi = 0; mi < 2; mi++) {
            int b0r = wm + mi * 16 + grp;          // batch row
            #pragma unroll
            for (int ni = 0; ni < 4; ni++) {
                int ncol = n0 + wn + ni * 8 + q * 2;
                float bb0 = bih[ncol], bb1 = bih[ncol + 1];
                float* g0 = giw + ((size_t)b0r * seq + tn) * G3;
                float* g1 = giw + ((size_t)(b0r + 8) * seq + tn) * G3;
                *(float2*)&g0[ncol] = make_float2(acc[mi][ni][0] + bb0,
                                                  acc[mi][ni][1] + bb1);
                *(float2*)&g1[ncol] = make_float2(acc[mi][ni][2] + bb0,
                                                  acc[mi][ni][3] + bb1);
            }
        }
        return;
    }

    // ================= Recurrence branch (R13-exact) =================
    const float* gi  = isDec ? g_gid : g_gi[gru];
    float* hist      = isDec ? g_dhist : g_hist[gru];
    const float* bhh = gru ? bhh1 : bhh0;
    int rp = t & 1, wp = rp ^ 1;

    const __nv_bfloat16* hhi = g_hbf_hi[which][rp];
    const __nv_bfloat16* hlo = g_hbf_lo[which][rp];
    const __nv_bfloat16* whi = g_whh_hi[which];
    const __nv_bfloat16* wlo = g_whh_lo[which];

    int j0 = blockIdx.x * 16;

    // staging: 224 rows x 64 bf16 per chunk; thread owns 7 uint4 (fixed map)
    const __nv_bfloat16* srcp[7];
    unsigned dstw[7];
    #pragma unroll
    for (int i = 0; i < 7; i++) {
        int l = tid + i * 256;
        int row = l >> 3, col = l & 7;
        const __nv_bfloat16* base;
        if (row < 64)       base = hhi + row * Hh;                 // A hi (b=row)
        else if (row < 128) base = hlo + (row - 64) * Hh;          // A lo
        else {
            int rr = row - 128;
            int isLo = (rr >= 48); if (isLo) rr -= 48;
            int g = rr >> 4, jj = rr & 15;
            int wrow = g * Hh + j0 + jj;                           // gate row
            base = (isLo ? wlo : whi) + (size_t)wrow * Hh;
        }
        srcp[i] = base + col * 8;
        dstw[i] = row * WKPW + col * 4;
    }

    // warp decomposition: 8 warps = 4 m-frags x 2 n-halves (24 n each)
    int wm = (w >> 1) << 4;            // 0,16,32,48
    int wn = (w & 1) * 24;             // 0 or 24

    float acc[3][4];
    #pragma unroll
    for (int ni = 0; ni < 3; ni++)
        #pragma unroll
        for (int r = 0; r < 4; r++) acc[ni][r] = 0.f;

    uint4 pf[7];
    #pragma unroll
    for (int i = 0; i < 7; i++) pf[i] = *(const uint4*)(srcp[i]);

    for (int c = 0; c < 8; c++) {
        unsigned* buf = smn + (c & 1) * BUFW;
        #pragma unroll
        for (int i = 0; i < 7; i++) *(uint4*)(buf + dstw[i]) = pf[i];
        __syncthreads();
        if (c < 7) {
            #pragma unroll
            for (int i = 0; i < 7; i++)
                pf[i] = *(const uint4*)(srcp[i] + (c + 1) * 64);
        }
        const unsigned* A = buf;                 // rows 0..127 (hi/lo)
        const unsigned* B = buf + 128 * WKPW;    // rows 0..95 (hi/lo)
        #pragma unroll
        for (int p = 0; p < 3; p++) {
            int aoff = (p == 1) ? 64 * WKPW : 0;   // pass1: A = h_lo
            int boff = (p == 2) ? 48 * WKPW : 0;   // pass2: B = W_lo
            #pragma unroll
            for (int ks = 0; ks < 4; ks++) {
                int kb = ks * 8;
                unsigned a[4], bfr[3][2];
                int r0 = aoff + (wm + grp) * WKPW;
                int r1 = aoff + (wm + grp + 8) * WKPW;
                a[0] = A[r0 + kb + q];
                a[1] = A[r1 + kb + q];
                a[2] = A[r0 + kb + q + 4];
                a[3] = A[r1 + kb + q + 4];
                #pragma unroll
                for (int ni = 0; ni < 3; ni++) {
                    int rn = boff + (wn + ni * 8 + grp) * WKPW;
                    bfr[ni][0] = B[rn + kb + q];
                    bfr[ni][1] = B[rn + kb + q + 4];
                }
                #pragma unroll
                for (int ni = 0; ni < 3; ni++)
                    mma_bf16(acc[ni], a, bfr[ni]);
            }
        }
        __syncthreads();
    }

    // gates -> smem buffer sg[b][rr]
    float* sg = (float*)(smn + 2 * BUFW);
    #pragma unroll
    for (int ni = 0; ni < 3; ni++) {
        int n = wn + ni * 8 + q * 2;
        *(float2*)&sg[(wm + grp) * SGP + n]     = make_float2(acc[ni][0], acc[ni][1]);
        *(float2*)&sg[(wm + grp + 8) * SGP + n] = make_float2(acc[ni][2], acc[ni][3]);
    }
    __syncthreads();

    // fused GRU pointwise: 1024 items (b, jj), 4 per thread
    __nv_bfloat16* ohi = g_hbf_hi[which][wp];
    __nv_bfloat16* olo = g_hbf_lo[which][wp];
    #pragma unroll
    for (int it = 0; it < 4; it++) {
        int idx = tid + it * 256;
        int b = idx & 63, jj = idx >> 6;
        int j = j0 + jj;
        const float* g = gi + ((size_t)b * seq + t) * G3;
        float pr = g[j]        + sg[b * SGP + jj]      + bhh[j];
        float pz = g[Hh + j]   + sg[b * SGP + 16 + jj] + bhh[Hh + j];
        float hn = sg[b * SGP + 32 + jj] + bhh[2 * Hh + j];
        float r = fsigmoid(pr);
        float z = fsigmoid(pz);
        float nn = tanhf(g[2 * Hh + j] + r * hn);
        float hold = hist[(size_t)t * HB + j * Bb + b];
        float ho = (1.f - z) * nn + z * hold;
        hist[(size_t)(t + 1) * HB + j * Bb + b] = ho;
        __nv_bfloat16 hh = __float2bfloat16(ho);
        ohi[b * Hh + j] = hh;
        olo[b * Hh + j] = __float2bfloat16(ho - __bfloat162float(hh));
    }
}

// ---------------------------------------------------------------------------
// score_enc[b][gru*S + t] = sum_j relu(h_{t+1}[j][b]) * w_enc[j]
// ---------------------------------------------------------------------------
__global__ __launch_bounds__(64) void score_kernel(const float* __restrict__ out_w) {
    int t = blockIdx.x, gru = blockIdx.y, b = threadIdx.x;
    const float* hrow = g_hist[gru] + (size_t)(t + 1) * HB;
    float acc = 0.f;
    for (int j = 0; j < Hh; j++)
        acc += fmaxf(hrow[j * Bb + b], 0.f) * out_w[j];
    g_score[b * (2 * Ss) + gru * Ss + t] = acc;
}

// ---------------------------------------------------------------------------
// enc_hidden (decoder h0) = tanh(cat(pre_h, post_h) @ enc_fc_w^T + enc_fc_b)
// also emits the decoder's hbf hi/lo for the first mma step
// ---------------------------------------------------------------------------
__global__ __launch_bounds__(64) void ench_kernel(const float* __restrict__ enc_fc_w,
                                                  const float* __restrict__ enc_fc_b) {
    int i = blockIdx.x, b = threadIdx.x;
    const float* w = enc_fc_w + (size_t)i * (2 * Hh);
    const float* hp0 = g_hist[0] + (size_t)Ss * HB;
    const float* hp1 = g_hist[1] + (size_t)Ss * HB;
    float acc = enc_fc_b[i];
    for (int q = 0; q < Hh; q++) acc += hp0[q * Bb + b] * w[q];
    for (int q = 0; q < Hh; q++) acc += hp1[q * Bb + b] * w[Hh + q];
    float th = tanhf(acc);
    g_dhist[i * Bb + b] = th;
    __nv_bfloat16 hh = __float2bfloat16(th);
    g_hbf_hi[2][0][b * Hh + i] = hh;
    g_hbf_lo[2][0][b * Hh + i] = __float2bfloat16(th - __bfloat162float(hh));
}

// ---------------------------------------------------------------------------
// decoder hidden score: hsc[t][b] = relu(hdec_{t+1}[:,b]) . w_hid + out_b
// ---------------------------------------------------------------------------
__global__ __launch_bounds__(64) void hsc_kernel(const float* __restrict__ out_w,
                                                 const float* __restrict__ out_b) {
    int t = blockIdx.x, b = threadIdx.x;
    const float* hrow = g_dhist + (size_t)(t + 1) * HB;
    float acc = 0.f;
    for (int j = 0; j < Hh; j++)
        acc += fmaxf(hrow[j * Bb + b], 0.f) * out_w[Hh + j];
    g_hsc[t * Bb + b] = acc + out_b[0];
}

// ---------------------------------------------------------------------------
// probs: out_pre[b][t][s] = sigmoid(score[b][s] + hsc[t][b]); post analogous
// ---------------------------------------------------------------------------
__global__ __launch_bounds__(256) void probs_kernel(float* __restrict__ out) {
    int bt = blockIdx.x;
    int b = bt >> 6, t = bt & 63;
    float hs = g_hsc[t * Bb + b];
    const float* sc = g_score + b * (2 * Ss);
    float* out_pre  = out + (size_t)bt * Ss;
    float* out_post = out + (size_t)Bb * Tt * Ss + (size_t)bt * Ss;
    #pragma unroll
    for (int it = 0; it < 4; it++) {
        int s2 = it * 256 + threadIdx.x;
        float l = sc[s2] + hs;
        float p = 1.f / (1.f + expf(-l));
        if (s2 < Ss) out_pre[s2] = p;
        else         out_post[s2 - Ss] = p;
    }
}

// ---------------------------------------------------------------------------
// launch
// ---------------------------------------------------------------------------
extern "C" void kernel_launch(void* const* d_in, const int* in_sizes, int n_in,
                              void* d_out, int out_size) {
    const int*   pre_seq   = (const int*)  d_in[0];
    const int*   post_seq  = (const int*)  d_in[1];
    const int*   trg       = (const int*)  d_in[2];
    const float* emb       = (const float*)d_in[3];
    const float* pre_Wih   = (const float*)d_in[4];
    const float* pre_Whh   = (const float*)d_in[5];
    const float* pre_bih   = (const float*)d_in[6];
    const float* pre_bhh   = (const float*)d_in[7];
    const float* post_Wih  = (const float*)d_in[8];
    const float* post_Whh  = (const float*)d_in[9];
    const float* post_bih  = (const float*)d_in[10];
    const float* post_bhh  = (const float*)d_in[11];
    const float* enc_fc_w  = (const float*)d_in[12];
    const float* enc_fc_b  = (const float*)d_in[13];
    const float* dec_Wih   = (const float*)d_in[14];
    const float* dec_Whh   = (const float*)d_in[15];
    const float* dec_bih   = (const float*)d_in[16];
    const float* dec_bhh   = (const float*)d_in[17];
    const float* out_w     = (const float*)d_in[18];
    const float* out_b     = (const float*)d_in[19];
    float* out = (float*)d_out;

    cudaFuncSetAttribute(gru_mma_step,
                         cudaFuncAttributeMaxDynamicSharedMemorySize, GRU_SMEM);

    // h0, decoder tokens, bf16 conversions (gi operands + Whh hi/lo splits)
    init_kernel<<<128, 256>>>();
    dectok_kernel<<<16, 256>>>(pre_seq, trg);
    prep_kernel<<<(Vv * Dd + 255) / 256, 256>>>(emb, 0, Vv * Dd);
    prep_kernel<<<(G3 * Dd + 255) / 256, 256>>>(pre_Wih,  1, G3 * Dd);
    prep_kernel<<<(G3 * Dd + 255) / 256, 256>>>(post_Wih, 2, G3 * Dd);
    prep_kernel<<<(G3 * Dd + 255) / 256, 256>>>(dec_Wih,  3, G3 * Dd);
    prep_whh<<<(G3 * Hh + 255) / 256, 256>>>(pre_Whh,  0);
    prep_whh<<<(G3 * Hh + 255) / 256, 256>>>(post_Whh, 1);
    prep_whh<<<(G3 * Hh + 255) / 256, 256>>>(dec_Whh,  2);

    // Prologues: gi[:,0,:] for both encoders and the decoder (GEMM CTAs only)
    gru_mma_step<<<dim3(12, 2), 256, GRU_SMEM>>>(0, -1, 0,
        pre_bhh, post_bhh, pre_bih, post_bih, pre_seq, post_seq);
    gru_mma_step<<<dim3(12, 1), 256, GRU_SMEM>>>(1, -1, 0,
        dec_bhh, dec_bhh, dec_bih, dec_bih, nullptr, nullptr);

    // Encoder recurrences; each step launch also carries 12 GEMM CTAs
    // computing gi[:, t+1, :] on the otherwise-idle SMs (88 CTAs, one wave)
    for (int t = 0; t < Ss; t++)
        gru_mma_step<<<dim3(32 + 12, 2), 256, GRU_SMEM>>>(0, t, 32,
            pre_bhh, post_bhh, pre_bih, post_bih, pre_seq, post_seq);

    // score_enc over all encoder outputs; decoder initial hidden (+ hbf)
    score_kernel<<<dim3(Ss, 2), 64>>>(out_w);
    ench_kernel<<<Hh, 64>>>(enc_fc_w, enc_fc_b);

    // Decoder recurrence (same fused structure)
    for (int t = 0; t < Tt; t++)
        gru_mma_step<<<dim3(32 + 12, 1), 256, GRU_SMEM>>>(1, t, 32,
            dec_bhh, dec_bhh, dec_bih, dec_bih, nullptr, nullptr);

    // Logits -> probabilities -> output
    hsc_kernel<<<Tt, 64>>>(out_w, out_b);
    probs_kernel<<<Bb * Tt, 256>>>(out);
}

// round 17
// speedup vs baseline: 1.9990x; 1.0619x over previous
#include <cuda_runtime.h>
#include <cuda_bf16.h>
#include <math.h>
#include <stdint.h>

// Problem dims
#define Bb   64
#define Ss   512
#define Tt   64
#define Hh   512
#define Dd   512
#define G3   1536          // 3*H
#define HB   (Hh*Bb)       // 32768, one hidden state in [j][b] layout
#define Vv   32000

// ---------------------------------------------------------------------------
// Scratch (device globals; no allocations allowed)
// ---------------------------------------------------------------------------
__device__ __align__(16) float g_gi[2][(size_t)Bb*Ss*G3];   // pre/post gate inputs [b][s][g]
__device__ __align__(16) float g_gid[(size_t)Bb*Tt*G3];     // decoder gate inputs  [b][t][g]
__device__ __align__(16) float g_hist[2][(size_t)(Ss+1)*HB];// encoder h history [t][j][b]
__device__ __align__(16) float g_dhist[(size_t)(Tt+1)*HB];  // decoder h history [t][j][b]
__device__ __align__(16) float g_score[Bb*2*Ss];            // score_enc [b][s2]
__device__ __align__(16) float g_hsc[Tt*Bb];                // decoder hidden scores [t][b]
__device__ int   g_dtok[Bb*Tt];                             // decoder input tokens

// bf16 operands for the gate-input GEMMs
__device__ __align__(16) __nv_bfloat16 g_emb_bf[(size_t)Vv*Dd];
__device__ __align__(16) __nv_bfloat16 g_w_bf[3][(size_t)G3*Dd];

// split-bf16 recurrence operands: Whh hi (static) and h hi/lo (ping-pong)
__device__ __align__(16) __nv_bfloat16 g_whh_hi[3][(size_t)G3*Hh];  // [gru 0,1,2=dec]
__device__ __align__(16) __nv_bfloat16 g_hbf_hi[3][2][Bb*Hh];       // [gru][parity][b*512+k]
__device__ __align__(16) __nv_bfloat16 g_hbf_lo[3][2][Bb*Hh];

// ---------------------------------------------------------------------------
// init: zero h0 (fp32 + bf16 split) for both encoder GRUs
// ---------------------------------------------------------------------------
__global__ void init_kernel() {
    int i = blockIdx.x * blockDim.x + threadIdx.x;
    if (i < HB) {
        g_hist[0][i] = 0.f; g_hist[1][i] = 0.f;
        __nv_bfloat16 z = __float2bfloat16(0.f);
        g_hbf_hi[0][0][i] = z; g_hbf_lo[0][0][i] = z;
        g_hbf_hi[1][0][i] = z; g_hbf_lo[1][0][i] = z;
    }
}

// decoder tokens: [pre_seq[:, -1:], trg[:, :-1]]
__global__ void dectok_kernel(const int* __restrict__ pre_seq,
                              const int* __restrict__ trg) {
    int idx = blockIdx.x * blockDim.x + threadIdx.x;
    if (idx >= Bb * Tt) return;
    int b = idx >> 6, t = idx & 63;
    g_dtok[idx] = (t == 0) ? pre_seq[b * Ss + (Ss - 1)] : trg[b * Tt + t - 1];
}

// fp32 -> bf16 conversion. which: 0=emb, 1..3 = W[0..2]
__global__ void prep_kernel(const float* __restrict__ src, int which, int n) {
    int i = blockIdx.x * blockDim.x + threadIdx.x;
    if (i >= n) return;
    __nv_bfloat16* d = (which == 0) ? g_emb_bf : g_w_bf[which - 1];
    d[i] = __float2bfloat16(src[i]);
}

// fp32 -> hi bf16 of Whh. which: 0,1 = encoders, 2 = decoder
__global__ void prep_whh(const float* __restrict__ src, int which) {
    int i = blockIdx.x * blockDim.x + threadIdx.x;
    if (i >= G3 * Hh) return;
    g_whh_hi[which][i] = __float2bfloat16(src[i]);
}

// ---------------------------------------------------------------------------
// bf16 mma.sync m16n8k16 (HMMA path; compiles at compute_103 family target)
// ---------------------------------------------------------------------------
__device__ __forceinline__ void mma_bf16(float* d, const unsigned* a, const unsigned* b) {
    asm volatile(
        "mma.sync.aligned.m16n8k16.row.col.f32.bf16.bf16.f32 "
        "{%0,%1,%2,%3}, {%4,%5,%6,%7}, {%8,%9}, {%0,%1,%2,%3};"
        : "+f"(d[0]), "+f"(d[1]), "+f"(d[2]), "+f"(d[3])
        : "r"(a[0]), "r"(a[1]), "r"(a[2]), "r"(a[3]), "r"(b[0]), "r"(b[1]));
}

__device__ __forceinline__ float fsigmoid(float x) {
    return 1.f / (1.f + __expf(-x));
}

// ---------------------------------------------------------------------------
// Fused step kernel. Per launch (grid x = recCnt + 12, y = nGru):
//  bx <  recCnt : GRU recurrence for step t (HMMA, 2 split passes:
//                 Whi*hhi + Whi*hlo — h error corrected, W at bf16)
//  bx >= recCnt : GEMM CTAs computing gi[:, t+1, n0:n0+128)
//                 (prologue: recCnt=0, t=-1 -> computes gi[:,0,:])
// Shared stage buffers: 192 rows x 64 bf16 (GEMM uses all 192; rec uses 176).
// ---------------------------------------------------------------------------
#define WKPW 36                    // stage row pitch in words (64 bf16 + pad)
#define BUFW (192 * WKPW)          // words per stage buffer (192 rows)
#define SGP  50                    // gate-buffer pitch (floats)
#define GRU_SMEM ((2 * BUFW) * 4 + Bb * SGP * 4)

__global__ __launch_bounds__(256) void gru_mma_step(
    int isDec, int t, int recCnt,
    const float* __restrict__ bhh0, const float* __restrict__ bhh1,
    const float* __restrict__ bih0, const float* __restrict__ bih1,
    const int* __restrict__ tok0, const int* __restrict__ tok1)
{
    extern __shared__ __align__(16) unsigned smn[];
    int gru = blockIdx.y;
    int which = isDec ? 2 : gru;
    int seq = isDec ? Tt : Ss;
    int tid = threadIdx.x;
    int w = tid >> 5, lane = tid & 31;
    int grp = lane >> 2, q = lane & 3;

    if ((int)blockIdx.x >= recCnt) {
        // ============ GEMM branch: gi[:, t+1, n0..n0+128), K chunked 64 ============
        int tn = t + 1;
        if (tn >= seq) return;
        int gx = blockIdx.x - recCnt;
        int n0 = gx * 128;
        const int* toks = isDec ? g_dtok : (gru ? tok1 : tok0);
        const __nv_bfloat16* Wg = g_w_bf[which];
        const float* bih = gru ? bih1 : bih0;
        float* giw = isDec ? g_gid : g_gi[gru];

        // staging: 192 rows (64 A=emb, 128 B=Wih) x 64 bf16; 6 uint4/thread
        const __nv_bfloat16* srcp[6];
        unsigned dstw[6];
        #pragma unroll
        for (int i = 0; i < 6; i++) {
            int l = tid + i * 256;
            int row = l >> 3, col = l & 7;
            const __nv_bfloat16* base;
            if (row < 64) {
                int tok = toks[row * seq + tn];
                base = g_emb_bf + (size_t)tok * Dd;
            } else {
                base = Wg + (size_t)(n0 + row - 64) * Dd;
            }
            srcp[i] = base + col * 8;
            dstw[i] = row * WKPW + col * 4;
        }

        int wm = (w >> 2) << 5;        // 0 or 32 (batch)
        int wn = (w & 3) << 5;         // 0,32,64,96 (n within 128)

        float acc[2][4][4];
        #pragma unroll
        for (int mi = 0; mi < 2; mi++)
            #pragma unroll
            for (int ni = 0; ni < 4; ni++)
                #pragma unroll
                for (int r = 0; r < 4; r++) acc[mi][ni][r] = 0.f;

        uint4 pf[6];
        #pragma unroll
        for (int i = 0; i < 6; i++) pf[i] = *(const uint4*)(srcp[i]);

        for (int c = 0; c < 8; c++) {
            unsigned* buf = smn + (c & 1) * BUFW;
            #pragma unroll
            for (int i = 0; i < 6; i++) *(uint4*)(buf + dstw[i]) = pf[i];
            __syncthreads();
            if (c < 7) {
                #pragma unroll
                for (int i = 0; i < 6; i++)
                    pf[i] = *(const uint4*)(srcp[i] + (c + 1) * 64);
            }
            const unsigned* A = buf;                // rows 0..63 (batch)
            const unsigned* B = buf + 64 * WKPW;    // rows 0..127 (n)
            #pragma unroll
            for (int ks = 0; ks < 4; ks++) {
                int kb = ks * 8;
                unsigned a[2][4], bfr[4][2];
                #pragma unroll
                for (int mi = 0; mi < 2; mi++) {
                    int r0 = (wm + mi * 16 + grp) * WKPW;
                    int r1 = r0 + 8 * WKPW;
                    a[mi][0] = A[r0 + kb + q];
                    a[mi][1] = A[r1 + kb + q];
                    a[mi][2] = A[r0 + kb + q + 4];
                    a[mi][3] = A[r1 + kb + q + 4];
                }
                #pragma unroll
                for (int ni = 0; ni < 4; ni++) {
                    int rn = (wn + ni * 8 + grp) * WKPW;
                    bfr[ni][0] = B[rn + kb + q];
                    bfr[ni][1] = B[rn + kb + q + 4];
                }
                #pragma unroll
                for (int mi = 0; mi < 2; mi++)
                    #pragma unroll
                    for (int ni = 0; ni < 4; ni++)
                        mma_bf16(acc[mi][ni], a[mi], bfr[ni]);
            }
            __syncthreads();
        }

        #pragma unroll
        for (int mi = 0; mi < 2; mi++) {
            int b0r = wm + mi * 16 + grp;          // batch row
            #pragma unroll
            for (int ni = 0; ni < 4; ni++) {
                int ncol = n0 + wn + ni * 8 + q * 2;
                float bb0 = bih[ncol], bb1 = bih[ncol + 1];
                float* g0 = giw + ((size_t)b0r * seq + tn) * G3;
                float* g1 = giw + ((size_t)(b0r + 8) * seq + tn) * G3;
                *(float2*)&g0[ncol] = make_float2(acc[mi][ni][0] + bb0,
                                                  acc[mi][ni][1] + bb1);
                *(float2*)&g1[ncol] = make_float2(acc[mi][ni][2] + bb0,
                                                  acc[mi][ni][3] + bb1);
            }
        }
        return;
    }

    // ================= Recurrence branch (2 split passes) =================
    const float* gi  = isDec ? g_gid : g_gi[gru];
    float* hist      = isDec ? g_dhist : g_hist[gru];
    const float* bhh = gru ? bhh1 : bhh0;
    int rp = t & 1, wp = rp ^ 1;

    const __nv_bfloat16* hhi = g_hbf_hi[which][rp];
    const __nv_bfloat16* hlo = g_hbf_lo[which][rp];
    const __nv_bfloat16* whi = g_whh_hi[which];

    int j0 = blockIdx.x * 16;

    // staging: 176 rows x 64 bf16 per chunk (64 hhi, 64 hlo, 48 whi);
    // 1408 uint4 over 256 threads = 5.5 iters (6th iter: tid<128 only)
    const __nv_bfloat16* srcp[6];
    unsigned dstw[6];
    bool tail = (tid < 128);
    #pragma unroll
    for (int i = 0; i < 6; i++) {
        int l = tid + i * 256;
        if (l >= 1408) l = tid;                    // inert remap (not stored)
        int row = l >> 3, col = l & 7;
        const __nv_bfloat16* base;
        if (row < 64)       base = hhi + row * Hh;                 // A hi (b=row)
        else if (row < 128) base = hlo + (row - 64) * Hh;          // A lo
        else {
            int rr = row - 128;                    // 0..47
            int g = rr >> 4, jj = rr & 15;
            base = whi + (size_t)(g * Hh + j0 + jj) * Hh;          // gate row
        }
        srcp[i] = base + col * 8;
        dstw[i] = row * WKPW + col * 4;
    }

    // warp decomposition: 8 warps = 4 m-frags x 2 n-halves (24 n each)
    int wm = (w >> 1) << 4;            // 0,16,32,48
    int wn = (w & 1) * 24;             // 0 or 24

    float acc[3][4];
    #pragma unroll
    for (int ni = 0; ni < 3; ni++)
        #pragma unroll
        for (int r = 0; r < 4; r++) acc[ni][r] = 0.f;

    uint4 pf[6];
    #pragma unroll
    for (int i = 0; i < 6; i++) pf[i] = *(const uint4*)(srcp[i]);

    for (int c = 0; c < 8; c++) {
        unsigned* buf = smn + (c & 1) * BUFW;
        #pragma unroll
        for (int i = 0; i < 5; i++) *(uint4*)(buf + dstw[i]) = pf[i];
        if (tail) *(uint4*)(buf + dstw[5]) = pf[5];
        __syncthreads();
        if (c < 7) {
            #pragma unroll
            for (int i = 0; i < 6; i++)
                pf[i] = *(const uint4*)(srcp[i] + (c + 1) * 64);
        }
        const unsigned* A = buf;                 // rows 0..127 (h hi/lo)
        const unsigned* B = buf + 128 * WKPW;    // rows 0..47 (W hi)
        #pragma unroll
        for (int p = 0; p < 2; p++) {
            int aoff = p ? 64 * WKPW : 0;          // pass1: A = h_lo
            #pragma unroll
            for (int ks = 0; ks < 4; ks++) {
                int kb = ks * 8;
                unsigned a[4], bfr[3][2];
                int r0 = aoff + (wm + grp) * WKPW;
                int r1 = aoff + (wm + grp + 8) * WKPW;
                a[0] = A[r0 + kb + q];
                a[1] = A[r1 + kb + q];
                a[2] = A[r0 + kb + q + 4];
                a[3] = A[r1 + kb + q + 4];
                #pragma unroll
                for (int ni = 0; ni < 3; ni++) {
                    int rn = (wn + ni * 8 + grp) * WKPW;
                    bfr[ni][0] = B[rn + kb + q];
                    bfr[ni][1] = B[rn + kb + q + 4];
                }
                #pragma unroll
                for (int ni = 0; ni < 3; ni++)
                    mma_bf16(acc[ni], a, bfr[ni]);
            }
        }
        __syncthreads();
    }

    // gates -> smem buffer sg[b][rr]
    float* sg = (float*)(smn + 2 * BUFW);
    #pragma unroll
    for (int ni = 0; ni < 3; ni++) {
        int n = wn + ni * 8 + q * 2;
        *(float2*)&sg[(wm + grp) * SGP + n]     = make_float2(acc[ni][0], acc[ni][1]);
        *(float2*)&sg[(wm + grp + 8) * SGP + n] = make_float2(acc[ni][2], acc[ni][3]);
    }
    __syncthreads();

    // fused GRU pointwise: 1024 items (b, jj), 4 per thread
    __nv_bfloat16* ohi = g_hbf_hi[which][wp];
    __nv_bfloat16* olo = g_hbf_lo[which][wp];
    #pragma unroll
    for (int it = 0; it < 4; it++) {
        int idx = tid + it * 256;
        int b = idx & 63, jj = idx >> 6;
        int j = j0 + jj;
        const float* g = gi + ((size_t)b * seq + t) * G3;
        float pr = g[j]        + sg[b * SGP + jj]      + bhh[j];
        float pz = g[Hh + j]   + sg[b * SGP + 16 + jj] + bhh[Hh + j];
        float hn = sg[b * SGP + 32 + jj] + bhh[2 * Hh + j];
        float r = fsigmoid(pr);
        float z = fsigmoid(pz);
        float nn = tanhf(g[2 * Hh + j] + r * hn);
        float hold = hist[(size_t)t * HB + j * Bb + b];
        float ho = (1.f - z) * nn + z * hold;
        hist[(size_t)(t + 1) * HB + j * Bb + b] = ho;
        __nv_bfloat16 hh = __float2bfloat16(ho);
        ohi[b * Hh + j] = hh;
        olo[b * Hh + j] = __float2bfloat16(ho - __bfloat162float(hh));
    }
}

// ---------------------------------------------------------------------------
// score_enc[b][gru*S + t] = sum_j relu(h_{t+1}[j][b]) * w_enc[j]
// 256 threads: b = tid&63, jj = tid>>6; coalesced reads over [j][b];
// smem tree-reduce the 4 jj-partials per b.
// ---------------------------------------------------------------------------
__global__ __launch_bounds__(256) void score_kernel(const float* __restrict__ out_w) {
    __shared__ float red[256];
    int t = blockIdx.x, gru = blockIdx.y;
    int tid = threadIdx.x;
    int b = tid & 63, jj = tid >> 6;
    const float* hrow = g_hist[gru] + (size_t)(t + 1) * HB;
    float acc = 0.f;
    for (int j = jj; j < Hh; j += 4)
        acc += fmaxf(hrow[j * Bb + b], 0.f) * out_w[j];
    red[tid] = acc;
    __syncthreads();
    if (tid < 128) red[tid] += red[tid + 128];
    __syncthreads();
    if (tid < 64)
        g_score[b * (2 * Ss) + gru * Ss + t] = red[tid] + red[tid + 64];
}

// ---------------------------------------------------------------------------
// enc_hidden (decoder h0) = tanh(cat(pre_h, post_h) @ enc_fc_w^T + enc_fc_b)
// also emits the decoder's hbf hi/lo for the first mma step
// ---------------------------------------------------------------------------
__global__ __launch_bounds__(64) void ench_kernel(const float* __restrict__ enc_fc_w,
                                                  const float* __restrict__ enc_fc_b) {
    int i = blockIdx.x, b = threadIdx.x;
    const float* w = enc_fc_w + (size_t)i * (2 * Hh);
    const float* hp0 = g_hist[0] + (size_t)Ss * HB;
    const float* hp1 = g_hist[1] + (size_t)Ss * HB;
    float acc = enc_fc_b[i];
    for (int q = 0; q < Hh; q++) acc += hp0[q * Bb + b] * w[q];
    for (int q = 0; q < Hh; q++) acc += hp1[q * Bb + b] * w[Hh + q];
    float th = tanhf(acc);
    g_dhist[i * Bb + b] = th;
    __nv_bfloat16 hh = __float2bfloat16(th);
    g_hbf_hi[2][0][b * Hh + i] = hh;
    g_hbf_lo[2][0][b * Hh + i] = __float2bfloat16(th - __bfloat162float(hh));
}

// ---------------------------------------------------------------------------
// decoder hidden score: hsc[t][b] = relu(hdec_{t+1}[:,b]) . w_hid + out_b
// ---------------------------------------------------------------------------
__global__ __launch_bounds__(64) void hsc_kernel(const float* __restrict__ out_w,
                                                 const float* __restrict__ out_b) {
    int t = blockIdx.x, b = threadIdx.x;
    const float* hrow = g_dhist + (size_t)(t + 1) * HB;
    float acc = 0.f;
    for (int j = 0; j < Hh; j++)
        acc += fmaxf(hrow[j * Bb + b], 0.f) * out_w[Hh + j];
    g_hsc[t * Bb + b] = acc + out_b[0];
}

// ---------------------------------------------------------------------------
// probs: out_pre[b][t][s] = sigmoid(score[b][s] + hsc[t][b]); post analogous
// ---------------------------------------------------------------------------
__global__ __launch_bounds__(256) void probs_kernel(float* __restrict__ out) {
    int bt = blockIdx.x;
    int b = bt >> 6, t = bt & 63;
    float hs = g_hsc[t * Bb + b];
    const float* sc = g_score + b * (2 * Ss);
    float* out_pre  = out + (size_t)bt * Ss;
    float* out_post = out + (size_t)Bb * Tt * Ss + (size_t)bt * Ss;
    #pragma unroll
    for (int it = 0; it < 4; it++) {
        int s2 = it * 256 + threadIdx.x;
        float l = sc[s2] + hs;
        float p = 1.f / (1.f + expf(-l));
        if (s2 < Ss) out_pre[s2] = p;
        else         out_post[s2 - Ss] = p;
    }
}

// ---------------------------------------------------------------------------
// launch
// ---------------------------------------------------------------------------
extern "C" void kernel_launch(void* const* d_in, const int* in_sizes, int n_in,
                              void* d_out, int out_size) {
    const int*   pre_seq   = (const int*)  d_in[0];
    const int*   post_seq  = (const int*)  d_in[1];
    const int*   trg       = (const int*)  d_in[2];
    const float* emb       = (const float*)d_in[3];
    const float* pre_Wih   = (const float*)d_in[4];
    const float* pre_Whh   = (const float*)d_in[5];
    const float* pre_bih   = (const float*)d_in[6];
    const float* pre_bhh   = (const float*)d_in[7];
    const float* post_Wih  = (const float*)d_in[8];
    const float* post_Whh  = (const float*)d_in[9];
    const float* post_bih  = (const float*)d_in[10];
    const float* post_bhh  = (const float*)d_in[11];
    const float* enc_fc_w  = (const float*)d_in[12];
    const float* enc_fc_b  = (const float*)d_in[13];
    const float* dec_Wih   = (const float*)d_in[14];
    const float* dec_Whh   = (const float*)d_in[15];
    const float* dec_bih   = (const float*)d_in[16];
    const float* dec_bhh   = (const float*)d_in[17];
    const float* out_w     = (const float*)d_in[18];
    const float* out_b     = (const float*)d_in[19];
    float* out = (float*)d_out;

    cudaFuncSetAttribute(gru_mma_step,
                         cudaFuncAttributeMaxDynamicSharedMemorySize, GRU_SMEM);

    // h0, decoder tokens, bf16 conversions (gi operands + Whh hi)
    init_kernel<<<128, 256>>>();
    dectok_kernel<<<16, 256>>>(pre_seq, trg);
    prep_kernel<<<(Vv * Dd + 255) / 256, 256>>>(emb, 0, Vv * Dd);
    prep_kernel<<<(G3 * Dd + 255) / 256, 256>>>(pre_Wih,  1, G3 * Dd);
    prep_kernel<<<(G3 * Dd + 255) / 256, 256>>>(post_Wih, 2, G3 * Dd);
    prep_kernel<<<(G3 * Dd + 255) / 256, 256>>>(dec_Wih,  3, G3 * Dd);
    prep_whh<<<(G3 * Hh + 255) / 256, 256>>>(pre_Whh,  0);
    prep_whh<<<(G3 * Hh + 255) / 256, 256>>>(post_Whh, 1);
    prep_whh<<<(G3 * Hh + 255) / 256, 256>>>(dec_Whh,  2);

    // Prologues: gi[:,0,:] for both encoders and the decoder (GEMM CTAs only)
    gru_mma_step<<<dim3(12, 2), 256, GRU_SMEM>>>(0, -1, 0,
        pre_bhh, post_bhh, pre_bih, post_bih, pre_seq, post_seq);
    gru_mma_step<<<dim3(12, 1), 256, GRU_SMEM>>>(1, -1, 0,
        dec_bhh, dec_bhh, dec_bih, dec_bih, nullptr, nullptr);

    // Encoder recurrences; each step launch also carries 12 GEMM CTAs
    // computing gi[:, t+1, :] on the otherwise-idle SMs (88 CTAs, one wave)
    for (int t = 0; t < Ss; t++)
        gru_mma_step<<<dim3(32 + 12, 2), 256, GRU_SMEM>>>(0, t, 32,
            pre_bhh, post_bhh, pre_bih, post_bih, pre_seq, post_seq);

    // score_enc over all encoder outputs; decoder initial hidden (+ hbf)
    score_kernel<<<dim3(Ss, 2), 256>>>(out_w);
    ench_kernel<<<Hh, 64>>>(enc_fc_w, enc_fc_b);

    // Decoder recurrence (same fused structure)
    for (int t = 0; t < Tt; t++)
        gru_mma_step<<<dim3(32 + 12, 1), 256, GRU_SMEM>>>(1, t, 32,
            dec_bhh, dec_bhh, dec_bih, dec_bih, nullptr, nullptr);

    // Logits -> probabilities -> output
    hsc_kernel<<<Tt, 64>>>(out_w, out_b);
    probs_kernel<<<Bb * Tt, 256>>>(out);
}